// round 12
// baseline (speedup 1.0000x reference)
#include <cuda_runtime.h>
#include <cuda_bf16.h>
#include <cstdint>

// Problem constants
#define S_LEN  4096
#define EMB    512
#define HEADS  8
#define DH     64
#define BATCH  2
#define GROUPS 32
#define GSIZE  65536
#define GN_EPS 100000.0f
#define QSCALE 0.125f   // 1/sqrt(64)

// Scratch (device globals; allocation-free rule)
__device__ __nv_bfloat16 g_xh[BATCH * S_LEN * EMB];        // normalized input, [b][s][d]
__device__ __nv_bfloat16 g_oh[BATCH * S_LEN * EMB];        // attention out, [b][s][h*64+d]
__device__ __nv_bfloat16 g_wh[4 * EMB * EMB];              // bf16 weights: q,k,v,o concat
__device__ float g_mu[BATCH * GROUPS];
__device__ float g_rstd[BATCH * GROUPS];
__device__ __nv_bfloat16 g_qh[BATCH * HEADS * S_LEN * DH]; // [b][h][s][dh], pre-scaled 1/8
__device__ __nv_bfloat16 g_kh[BATCH * HEADS * S_LEN * DH]; // [b][h][s][dh]
__device__ __nv_bfloat16 g_vh[BATCH * HEADS * S_LEN * DH]; // [b][h][s][dh]
// Linear-attention small matrices
#define NBH (BATCH * HEADS)           // 16
#define MPCH 32                       // 128-seq chunks per head
#define MPSZ 4224                     // 64*64 M + 64 Ksum + 64 Vsum
__device__ float g_mp[NBH * MPCH * MPSZ];          // partials
__device__ __nv_bfloat16 g_mtb[NBH * 64 * 64];     // M^T per head, bf16
__device__ float g_ks[NBH * 64];                   // Ksum
__device__ float g_vs[NBH * 64];                   // Vsum

__device__ __forceinline__ void mma16816(float c[4], const uint32_t a[4],
                                         uint32_t b0, uint32_t b1) {
    asm volatile(
        "mma.sync.aligned.m16n8k16.row.col.f32.bf16.bf16.f32 "
        "{%0,%1,%2,%3},{%4,%5,%6,%7},{%8,%9},{%0,%1,%2,%3};\n"
        : "+f"(c[0]), "+f"(c[1]), "+f"(c[2]), "+f"(c[3])
        : "r"(a[0]), "r"(a[1]), "r"(a[2]), "r"(a[3]), "r"(b0), "r"(b1));
}
__device__ __forceinline__ uint32_t packbf(float x, float y) {
    uint32_t d;
    asm("cvt.rn.bf16x2.f32 %0, %1, %2;" : "=r"(d) : "f"(y), "f"(x));
    return d;
}
__device__ __forceinline__ float bflo(uint32_t u) { return __uint_as_float(u << 16); }
__device__ __forceinline__ float bfhi(uint32_t u) { return __uint_as_float(u & 0xffff0000u); }
__device__ __forceinline__ void ldsm4(uint32_t* r, const __nv_bfloat16* p) {
    uint32_t a = (uint32_t)__cvta_generic_to_shared((void*)p);
    asm volatile("ldmatrix.sync.aligned.m8n8.x4.shared.b16 {%0,%1,%2,%3}, [%4];\n"
        : "=r"(r[0]), "=r"(r[1]), "=r"(r[2]), "=r"(r[3]) : "r"(a));
}
__device__ __forceinline__ void cpasync16(void* smem, const void* gmem) {
    uint32_t s = (uint32_t)__cvta_generic_to_shared(smem);
    asm volatile("cp.async.cg.shared.global [%0], [%1], 16;\n" :: "r"(s), "l"(gmem));
}
#define CP_COMMIT() asm volatile("cp.async.commit_group;\n" ::: "memory")
#define CP_WAIT(N)  asm volatile("cp.async.wait_group %0;\n" :: "n"(N) : "memory")

// ---------------------------------------------------------------------------
// 1) GroupNorm statistics
// ---------------------------------------------------------------------------
__global__ void gn_stats(const float* __restrict__ in) {
    int g = blockIdx.x;
    const float4* p = (const float4*)(in + (size_t)g * GSIZE);
    float s = 0.f, s2 = 0.f;
    for (int i = threadIdx.x; i < GSIZE / 4; i += 1024) {
        float4 f = p[i];
        s  += f.x + f.y + f.z + f.w;
        s2 += f.x * f.x + f.y * f.y + f.z * f.z + f.w * f.w;
    }
    __shared__ float ss[32], ss2[32];
    #pragma unroll
    for (int o = 16; o > 0; o >>= 1) {
        s  += __shfl_down_sync(0xffffffffu, s,  o);
        s2 += __shfl_down_sync(0xffffffffu, s2, o);
    }
    int lane = threadIdx.x & 31, w = threadIdx.x >> 5;
    if (lane == 0) { ss[w] = s; ss2[w] = s2; }
    __syncthreads();
    if (threadIdx.x == 0) {
        float ts = 0.f, ts2 = 0.f;
        #pragma unroll
        for (int i = 0; i < 32; i++) { ts += ss[i]; ts2 += ss2[i]; }
        float mean = ts / (float)GSIZE;
        float var  = ts2 / (float)GSIZE - mean * mean;
        g_mu[g]   = mean;
        g_rstd[g] = rsqrtf(var + GN_EPS);
    }
}

// ---------------------------------------------------------------------------
// 2) Normalize + affine + transpose (B,D,S) -> (B,S,D), bf16 out.
// ---------------------------------------------------------------------------
__global__ __launch_bounds__(256) void norm_transpose(const float* __restrict__ in,
                                                      const float* __restrict__ gamma,
                                                      const float* __restrict__ beta) {
    __shared__ float tile[32][129];
    int b = blockIdx.z, tid = threadIdx.x;
    int d0 = blockIdx.y * 32, s0 = blockIdx.x * 128;
    #pragma unroll
    for (int i = 0; i < 4; i++) {
        int idx = tid + i * 256;
        int d = idx >> 5, s4 = idx & 31;
        int gd = d0 + d;
        float4 f = *(const float4*)(in + ((size_t)b * EMB + gd) * S_LEN + s0 + s4 * 4);
        int grp = b * GROUPS + (gd >> 4);
        float sc = g_rstd[grp] * gamma[gd];
        float sh = beta[gd] - g_mu[grp] * sc;
        tile[d][s4 * 4 + 0] = f.x * sc + sh;
        tile[d][s4 * 4 + 1] = f.y * sc + sh;
        tile[d][s4 * 4 + 2] = f.z * sc + sh;
        tile[d][s4 * 4 + 3] = f.w * sc + sh;
    }
    __syncthreads();
    #pragma unroll
    for (int k = 0; k < 2; k++) {
        int u = tid + k * 256;
        int s = u >> 2, c8 = (u & 3) * 8;
        uint32_t r[4];
        #pragma unroll
        for (int e = 0; e < 4; e++)
            r[e] = packbf(tile[c8 + 2 * e][s], tile[c8 + 2 * e + 1][s]);
        *(uint4*)(g_xh + ((size_t)b * S_LEN + s0 + s) * EMB + d0 + c8) = *(uint4*)r;
    }
}

// ---------------------------------------------------------------------------
// 2b) Weight conversion fp32 -> bf16
// ---------------------------------------------------------------------------
__global__ void wconv(const float* __restrict__ w0, const float* __restrict__ w1,
                      const float* __restrict__ w2, const float* __restrict__ w3) {
    const float* src = (blockIdx.y == 0) ? w0 : (blockIdx.y == 1) ? w1
                     : (blockIdx.y == 2) ? w2 : w3;
    __nv_bfloat16* dst = g_wh + (size_t)blockIdx.y * EMB * EMB;
    int i = blockIdx.x * 256 + threadIdx.x;
    float4 f = ((const float4*)src)[i];
    *(uint32_t*)(dst + (size_t)i * 4)     = packbf(f.x, f.y);
    *(uint32_t*)(dst + (size_t)i * 4 + 2) = packbf(f.z, f.w);
}

// ---------------------------------------------------------------------------
// 3) bf16 GEMM: tile 128x128x32, 256 threads (4m x 2n warps, warp 32x64),
//    2-stage cp.async ring, one sync per k-iter. Static smem 40 KB, regs
//    capped at 128 (launch_bounds 256,2) -> 2 CTAs/SM.
// ---------------------------------------------------------------------------
#define GBM 128
#define GBN 128
#define GBK 32
#define GPAD 40
#define STAGE_BF ((GBM + GBN) * GPAD)      // 10240 bf16 = 20480 B
#define NKS (EMB / GBK)                    // 16
#define SMEM_BYTES 40960                   // 2 stages (static, < 48 KB)

__device__ __forceinline__ void g_load_stage(const __nv_bfloat16* A, const __nv_bfloat16* Wb,
                                             int m0, int k0, __nv_bfloat16* S, int tid) {
    __nv_bfloat16* As = S;
    __nv_bfloat16* Bs = S + GBM * GPAD;
    #pragma unroll
    for (int i = 0; i < 2; i++) {
        int idx = tid + i * 256;
        int r = idx >> 2, q = idx & 3;
        cpasync16(As + r * GPAD + q * 8, A + (size_t)(m0 + r) * EMB + k0 + q * 8);
    }
    #pragma unroll
    for (int i = 0; i < 2; i++) {
        int idx = tid + i * 256;
        int r = idx >> 2, q = idx & 3;
        cpasync16(Bs + r * GPAD + q * 8, Wb + (size_t)r * EMB + k0 + q * 8);
    }
}

// acc[mi][ni]: mi = 2 x 16-row tiles (warp m=32), ni = 8 x 8-col tiles (warp n=64)
__device__ __forceinline__ void g_mainloop(const __nv_bfloat16* A, const __nv_bfloat16* Wb,
                                           int m0, float acc[2][8][4],
                                           char* smem_raw, int tid) {
    __nv_bfloat16* S0 = (__nv_bfloat16*)smem_raw;
    int w = tid >> 5, l = tid & 31;
    int wm = w & 3, wn = w >> 2;
    int lrow = l & 15, lcol = (l >> 4) * 8;

    g_load_stage(A, Wb, m0, 0, S0, tid);
    CP_COMMIT();

    for (int ks = 0; ks < NKS; ks++) {
        if (ks == 0) { CP_WAIT(0); } else { CP_WAIT(1); }
        __syncthreads();
        if (ks + 1 < NKS) {
            g_load_stage(A, Wb, m0, (ks + 1) * GBK, S0 + ((ks + 1) & 1) * STAGE_BF, tid);
            CP_COMMIT();
        }
        __nv_bfloat16* Sc = S0 + (ks & 1) * STAGE_BF;
        __nv_bfloat16* As = Sc;
        __nv_bfloat16* Bs = Sc + GBM * GPAD;
        #pragma unroll
        for (int kk = 0; kk < 2; kk++) {
            uint32_t af[2][4], bt[4][4];
            #pragma unroll
            for (int mi = 0; mi < 2; mi++)
                ldsm4(af[mi], As + (wm * 32 + mi * 16 + lrow) * GPAD + kk * 16 + lcol);
            #pragma unroll
            for (int t = 0; t < 4; t++)
                ldsm4(bt[t], Bs + (wn * 64 + t * 16 + lrow) * GPAD + kk * 16 + lcol);
            #pragma unroll
            for (int mi = 0; mi < 2; mi++)
                #pragma unroll
                for (int t = 0; t < 4; t++) {
                    mma16816(acc[mi][2 * t + 0], af[mi], bt[t][0], bt[t][2]);
                    mma16816(acc[mi][2 * t + 1], af[mi], bt[t][1], bt[t][3]);
                }
        }
        // no end-of-iter sync: next iter's top barrier protects buffer reuse
    }
}

// Fused Q/K/V projection: N spans 1536 concat rows of g_wh.
__global__ __launch_bounds__(256, 2) void gemm_qkv(const float* __restrict__ bq,
                                                   const float* __restrict__ bk,
                                                   const float* __restrict__ bv) {
    __shared__ __align__(16) char smem_raw[SMEM_BYTES];
    int tid = threadIdx.x, w = tid >> 5, l = tid & 31;
    int wm = w & 3, wn = w >> 2;
    int lr = l >> 2, cq = (l & 3) * 2;
    int n0g = blockIdx.x * GBN;          // 0..1408
    int mode = n0g >> 9;                 // 0=q 1=k 2=v
    int n0 = n0g & 511;
    int m0 = blockIdx.y * GBM;
    const float* bias = (mode == 0) ? bq : (mode == 1) ? bk : bv;

    float acc[2][8][4] = {};
    g_mainloop(g_xh, g_wh + (size_t)n0g * EMB, m0, acc, smem_raw, tid);

    int b   = m0 >> 12;
    int sm0 = m0 & 4095;

    __nv_bfloat16* dst = (mode == 0) ? g_qh : (mode == 1) ? g_kh : g_vh;
    const float sc = (mode == 0) ? QSCALE : 1.0f;
    #pragma unroll
    for (int mi = 0; mi < 2; mi++) {
        int s0 = sm0 + wm * 32 + mi * 16 + lr;
        #pragma unroll
        for (int ni = 0; ni < 8; ni++) {
            int nc = n0 + wn * 64 + ni * 8 + cq;     // 0..511 within mode
            int h = nc >> 6, d = nc & 63;
            size_t hb = (size_t)(b * HEADS + h) * S_LEN;
            float b0 = bias[nc], b1 = bias[nc + 1];
            *(uint32_t*)(dst + (hb + s0) * DH + d) =
                packbf((acc[mi][ni][0] + b0) * sc, (acc[mi][ni][1] + b1) * sc);
            *(uint32_t*)(dst + (hb + s0 + 8) * DH + d) =
                packbf((acc[mi][ni][2] + b0) * sc, (acc[mi][ni][3] + b1) * sc);
        }
    }
}

// Output projection + residual, fp32 [B,D,S] out. Two 64-col transpose passes,
// buffer [64 cols][132 rows] fp32 = 33.8 KB (row stride 528 B, 16B-aligned).
__global__ __launch_bounds__(256, 2) void gemm_out(const float* __restrict__ bias,
                                                   float* __restrict__ dout,
                                                   const float* __restrict__ residual) {
    __shared__ __align__(16) char smem_raw[SMEM_BYTES];
    int tid = threadIdx.x, w = tid >> 5, l = tid & 31;
    int wm = w & 3, wn = w >> 2;
    int lr = l >> 2, cq = (l & 3) * 2;
    int n0 = blockIdx.x * GBN;
    int m0 = blockIdx.y * GBM;

    float acc[2][8][4] = {};
    g_mainloop(g_oh, g_wh + (size_t)3 * EMB * EMB + (size_t)n0 * EMB, m0, acc, smem_raw, tid);

    int b   = m0 >> 12;
    int sm0 = m0 & 4095;

    float* Tf = (float*)smem_raw;                      // [64][132] fp32
    #pragma unroll
    for (int p = 0; p < 2; p++) {
        __syncthreads();
        if (wn == p) {
            #pragma unroll
            for (int mi = 0; mi < 2; mi++) {
                int rl = wm * 32 + mi * 16 + lr;       // 0..127
                #pragma unroll
                for (int ni = 0; ni < 8; ni++) {
                    int cl = ni * 8 + cq;              // 0..63 within half
                    float b0 = bias[n0 + p * 64 + cl], b1 = bias[n0 + p * 64 + cl + 1];
                    Tf[cl * 132 + rl]           = acc[mi][ni][0] + b0;
                    Tf[(cl + 1) * 132 + rl]     = acc[mi][ni][1] + b1;
                    Tf[cl * 132 + rl + 8]       = acc[mi][ni][2] + b0;
                    Tf[(cl + 1) * 132 + rl + 8] = acc[mi][ni][3] + b1;
                }
            }
        }
        __syncthreads();
        #pragma unroll
        for (int i = 0; i < 8; i++) {
            int idx = tid + i * 256;
            int dd = idx >> 5, ch = idx & 31;          // dd 0..63, ch 0..31
            float4 v = *(float4*)(Tf + dd * 132 + ch * 4);
            size_t oi = ((size_t)b * EMB + n0 + p * 64 + dd) * S_LEN + sm0 + ch * 4;
            float4 r = *(const float4*)(residual + oi);
            v.x += r.x; v.y += r.y; v.z += r.z; v.w += r.w;
            *(float4*)(dout + oi) = v;
        }
    }
}

// ---------------------------------------------------------------------------
// 4a) Linear attention: partial M^T = (K^T V)^T, Ksum, Vsum per (head, chunk).
// ---------------------------------------------------------------------------
__global__ __launch_bounds__(256) void m_partial() {
    __shared__ float Kf[128][64];                 // 32 KB
    __shared__ __nv_bfloat16 Vs[128][64];         // 16 KB
    int tid = threadIdx.x;
    int chunk = blockIdx.x, bh = blockIdx.y;
    const __nv_bfloat16* Kb = g_kh + ((size_t)bh * S_LEN + chunk * 128) * DH;
    const __nv_bfloat16* Vb = g_vh + ((size_t)bh * S_LEN + chunk * 128) * DH;
    #pragma unroll
    for (int i = 0; i < 4; i++) {
        int idx = tid + i * 256;
        int r = idx >> 3, q = idx & 7;
        uint4 u = *(const uint4*)(Kb + (size_t)r * DH + q * 8);
        uint32_t ws[4] = {u.x, u.y, u.z, u.w};
        #pragma unroll
        for (int e = 0; e < 4; e++) {
            Kf[r][q * 8 + 2 * e]     = bflo(ws[e]);
            Kf[r][q * 8 + 2 * e + 1] = bfhi(ws[e]);
        }
        *(uint4*)(&Vs[r][q * 8]) = *(const uint4*)(Vb + (size_t)r * DH + q * 8);
    }
    __syncthreads();

    int ti = tid & 15, tj = tid >> 4;
    int i0 = ti * 4, j0 = tj * 4;
    float acc[4][4] = {};
    #pragma unroll 4
    for (int s = 0; s < 128; s++) {
        float4 kf = *(float4*)(&Kf[s][i0]);
        uint2 vv = *(uint2*)(&Vs[s][j0]);
        float vf[4] = {bflo(vv.x), bfhi(vv.x), bflo(vv.y), bfhi(vv.y)};
        #pragma unroll
        for (int a = 0; a < 4; a++) {
            acc[a][0] += vf[a] * kf.x;
            acc[a][1] += vf[a] * kf.y;
            acc[a][2] += vf[a] * kf.z;
            acc[a][3] += vf[a] * kf.w;
        }
    }
    float* mp = g_mp + (size_t)(bh * MPCH + chunk) * MPSZ;
    #pragma unroll
    for (int a = 0; a < 4; a++)
        #pragma unroll
        for (int bb = 0; bb < 4; bb++)
            mp[(j0 + a) * 64 + i0 + bb] = acc[a][bb];     // Mt[j][i]

    if (tid < 64) {
        float s = 0.f;
        for (int r = 0; r < 128; r++) s += Kf[r][tid];
        mp[4096 + tid] = s;                               // Ksum
    } else if (tid < 128) {
        int j = tid - 64;
        float s = 0.f;
        for (int r = 0; r < 128; r++) {
            uint32_t u = (uint32_t)(*(const uint16_t*)&Vs[r][j]);
            s += __uint_as_float(u << 16);
        }
        mp[4160 + j] = s;                                 // Vsum
    }
}

// 4b) Reduce partials -> g_mtb (bf16), g_ks, g_vs.
__global__ void m_reduce() {
    int bh = blockIdx.x, tid = threadIdx.x;
    for (int e = tid; e < MPSZ; e += 256) {
        float s = 0.f;
        #pragma unroll 8
        for (int c = 0; c < MPCH; c++)
            s += g_mp[(size_t)(bh * MPCH + c) * MPSZ + e];
        if (e < 4096)      g_mtb[bh * 4096 + e] = __float2bfloat16(s);
        else if (e < 4160) g_ks[bh * 64 + e - 4096] = s;
        else               g_vs[bh * 64 + e - 4160] = s;
    }
}

// 4c) O = (Vsum + Q M) / (4096 + Q Ksum).
__global__ __launch_bounds__(128) void attn_lin() {
    __shared__ __align__(16) __nv_bfloat16 Mts[64 * 72];
    __shared__ float ks[64], vs[64];
    int tid = threadIdx.x, w = tid >> 5, l = tid & 31;
    int qt = blockIdx.x, bh = blockIdx.y;

    #pragma unroll
    for (int i = 0; i < 4; i++) {
        int idx = tid + i * 128;
        int r = idx >> 3, q = idx & 7;
        *(uint4*)(Mts + r * 72 + q * 8) = *(const uint4*)(g_mtb + bh * 4096 + r * 64 + q * 8);
    }
    if (tid < 64) ks[tid] = g_ks[bh * 64 + tid];
    else vs[tid - 64] = g_vs[bh * 64 + tid - 64];
    __syncthreads();

    const __nv_bfloat16* Qb = g_qh + (size_t)bh * S_LEN * DH;
    int cq = (l & 3) * 2;
    int rq = qt * 128 + w * 32 + (l >> 2);
    uint32_t qf[2][4][4];
    #pragma unroll
    for (int mi = 0; mi < 2; mi++) {
        int rr = rq + mi * 16;
        #pragma unroll
        for (int kk = 0; kk < 4; kk++) {
            int c = kk * 16 + cq;
            qf[mi][kk][0] = *(const uint32_t*)(Qb + (size_t)rr * DH + c);
            qf[mi][kk][1] = *(const uint32_t*)(Qb + (size_t)(rr + 8) * DH + c);
            qf[mi][kk][2] = *(const uint32_t*)(Qb + (size_t)rr * DH + c + 8);
            qf[mi][kk][3] = *(const uint32_t*)(Qb + (size_t)(rr + 8) * DH + c + 8);
        }
    }

    float oacc[2][8][4] = {};
    int lrow = l & 15, lcol = (l >> 4) * 8;
    #pragma unroll
    for (int kk = 0; kk < 4; kk++) {
        uint32_t bt[4][4];
        #pragma unroll
        for (int rg = 0; rg < 4; rg++)
            ldsm4(bt[rg], Mts + (rg * 16 + lrow) * 72 + kk * 16 + lcol);
        #pragma unroll
        for (int mi = 0; mi < 2; mi++)
            #pragma unroll
            for (int rg = 0; rg < 4; rg++) {
                mma16816(oacc[mi][2 * rg + 0], qf[mi][kk], bt[rg][0], bt[rg][2]);
                mma16816(oacc[mi][2 * rg + 1], qf[mi][kk], bt[rg][1], bt[rg][3]);
            }
    }

    int b = bh >> 3, h = bh & 7;
    #pragma unroll
    for (int mi = 0; mi < 2; mi++) {
        float p0 = 0.f, p1 = 0.f;
        #pragma unroll
        for (int kk = 0; kk < 4; kk++) {
            int c = kk * 16 + cq;
            uint32_t u0 = qf[mi][kk][0], u1 = qf[mi][kk][1];
            uint32_t u2 = qf[mi][kk][2], u3 = qf[mi][kk][3];
            p0 += bflo(u0) * ks[c]     + bfhi(u0) * ks[c + 1];
            p0 += bflo(u2) * ks[c + 8] + bfhi(u2) * ks[c + 9];
            p1 += bflo(u1) * ks[c]     + bfhi(u1) * ks[c + 1];
            p1 += bflo(u3) * ks[c + 8] + bfhi(u3) * ks[c + 9];
        }
        p0 += __shfl_xor_sync(0xffffffffu, p0, 1);
        p0 += __shfl_xor_sync(0xffffffffu, p0, 2);
        p1 += __shfl_xor_sync(0xffffffffu, p1, 1);
        p1 += __shfl_xor_sync(0xffffffffu, p1, 2);
        float i0 = 1.f / ((float)S_LEN + p0), i1 = 1.f / ((float)S_LEN + p1);
        int rr = rq + mi * 16;
        #pragma unroll
        for (int j = 0; j < 8; j++) {
            int col = j * 8 + cq;
            float a0 = (vs[col] + oacc[mi][j][0]) * i0;
            float a1 = (vs[col + 1] + oacc[mi][j][1]) * i0;
            float a2 = (vs[col] + oacc[mi][j][2]) * i1;
            float a3 = (vs[col + 1] + oacc[mi][j][3]) * i1;
            *(uint32_t*)(g_oh + ((size_t)(b * S_LEN + rr)) * EMB + h * DH + col) =
                packbf(a0, a1);
            *(uint32_t*)(g_oh + ((size_t)(b * S_LEN + rr + 8)) * EMB + h * DH + col) =
                packbf(a2, a3);
        }
    }
}

// ---------------------------------------------------------------------------
// Launch
// ---------------------------------------------------------------------------
extern "C" void kernel_launch(void* const* d_in, const int* in_sizes, int n_in,
                              void* d_out, int out_size) {
    const float* input = (const float*)d_in[0];
    const float* gamma = (const float*)d_in[1];
    const float* beta  = (const float*)d_in[2];
    const float* wq = (const float*)d_in[3];
    const float* bq = (const float*)d_in[4];
    const float* wk = (const float*)d_in[5];
    const float* bk = (const float*)d_in[6];
    const float* wv = (const float*)d_in[7];
    const float* bv = (const float*)d_in[8];
    const float* wo = (const float*)d_in[9];
    const float* bo = (const float*)d_in[10];
    float* out = (float*)d_out;

    gn_stats<<<BATCH * GROUPS, 1024>>>(input);
    wconv<<<dim3(256, 4), 256>>>(wq, wk, wv, wo);
    norm_transpose<<<dim3(S_LEN / 128, EMB / 32, BATCH), 256>>>(input, gamma, beta);

    gemm_qkv<<<dim3(3 * EMB / GBN, (BATCH * S_LEN) / GBM), 256>>>(bq, bk, bv);

    m_partial<<<dim3(MPCH, NBH), 256>>>();
    m_reduce<<<NBH, 256>>>();
    attn_lin<<<dim3(S_LEN / 128, NBH), 128>>>();

    gemm_out<<<dim3(EMB / GBN, (BATCH * S_LEN) / GBM), 256>>>(bo, out, input);
}

// round 13
// speedup vs baseline: 1.0002x; 1.0002x over previous
#include <cuda_runtime.h>
#include <cuda_bf16.h>
#include <cstdint>

// Problem constants
#define S_LEN  4096
#define EMB    512
#define HEADS  8
#define DH     64
#define BATCH  2
#define GROUPS 32
#define GSIZE  65536
#define GN_EPS 100000.0f
#define QSCALE 0.125f   // 1/sqrt(64)

// Scratch (device globals; allocation-free rule)
__device__ __nv_bfloat16 g_xh[BATCH * S_LEN * EMB];        // normalized input, [b][s][d]
__device__ __nv_bfloat16 g_oh[BATCH * S_LEN * EMB];        // attention out, [b][s][h*64+d]
__device__ __nv_bfloat16 g_wh[4 * EMB * EMB];              // bf16 weights: q,k,v,o concat
__device__ float g_mu[BATCH * GROUPS];
__device__ float g_rstd[BATCH * GROUPS];
__device__ __nv_bfloat16 g_qh[BATCH * HEADS * S_LEN * DH]; // [b][h][s][dh], pre-scaled 1/8
__device__ __nv_bfloat16 g_kh[BATCH * HEADS * S_LEN * DH]; // [b][h][s][dh]
__device__ __nv_bfloat16 g_vh[BATCH * HEADS * S_LEN * DH]; // [b][h][s][dh]
// Linear-attention small matrices
#define NBH (BATCH * HEADS)           // 16
#define MPCH 32                       // 128-seq chunks per head
#define MPSZ 4224                     // 64*64 M + 64 Ksum + 64 Vsum
__device__ float g_mp[NBH * MPCH * MPSZ];          // partials
__device__ __nv_bfloat16 g_mtb[NBH * 64 * 64];     // M^T per head, bf16
__device__ float g_ks[NBH * 64];                   // Ksum
__device__ float g_vs[NBH * 64];                   // Vsum

__device__ __forceinline__ void mma16816(float c[4], const uint32_t a[4],
                                         uint32_t b0, uint32_t b1) {
    asm volatile(
        "mma.sync.aligned.m16n8k16.row.col.f32.bf16.bf16.f32 "
        "{%0,%1,%2,%3},{%4,%5,%6,%7},{%8,%9},{%0,%1,%2,%3};\n"
        : "+f"(c[0]), "+f"(c[1]), "+f"(c[2]), "+f"(c[3])
        : "r"(a[0]), "r"(a[1]), "r"(a[2]), "r"(a[3]), "r"(b0), "r"(b1));
}
__device__ __forceinline__ uint32_t packbf(float x, float y) {
    uint32_t d;
    asm("cvt.rn.bf16x2.f32 %0, %1, %2;" : "=r"(d) : "f"(y), "f"(x));
    return d;
}
__device__ __forceinline__ float bflo(uint32_t u) { return __uint_as_float(u << 16); }
__device__ __forceinline__ float bfhi(uint32_t u) { return __uint_as_float(u & 0xffff0000u); }
__device__ __forceinline__ void ldsm4(uint32_t* r, const __nv_bfloat16* p) {
    uint32_t a = (uint32_t)__cvta_generic_to_shared((void*)p);
    asm volatile("ldmatrix.sync.aligned.m8n8.x4.shared.b16 {%0,%1,%2,%3}, [%4];\n"
        : "=r"(r[0]), "=r"(r[1]), "=r"(r[2]), "=r"(r[3]) : "r"(a));
}
__device__ __forceinline__ void cpasync16(void* smem, const void* gmem) {
    uint32_t s = (uint32_t)__cvta_generic_to_shared(smem);
    asm volatile("cp.async.cg.shared.global [%0], [%1], 16;\n" :: "r"(s), "l"(gmem));
}
#define CP_COMMIT() asm volatile("cp.async.commit_group;\n" ::: "memory")
#define CP_WAIT(N)  asm volatile("cp.async.wait_group %0;\n" :: "n"(N) : "memory")

// ---------------------------------------------------------------------------
// 1) GroupNorm statistics
// ---------------------------------------------------------------------------
__global__ void gn_stats(const float* __restrict__ in) {
    int g = blockIdx.x;
    const float4* p = (const float4*)(in + (size_t)g * GSIZE);
    float s = 0.f, s2 = 0.f;
    for (int i = threadIdx.x; i < GSIZE / 4; i += 1024) {
        float4 f = p[i];
        s  += f.x + f.y + f.z + f.w;
        s2 += f.x * f.x + f.y * f.y + f.z * f.z + f.w * f.w;
    }
    __shared__ float ss[32], ss2[32];
    #pragma unroll
    for (int o = 16; o > 0; o >>= 1) {
        s  += __shfl_down_sync(0xffffffffu, s,  o);
        s2 += __shfl_down_sync(0xffffffffu, s2, o);
    }
    int lane = threadIdx.x & 31, w = threadIdx.x >> 5;
    if (lane == 0) { ss[w] = s; ss2[w] = s2; }
    __syncthreads();
    if (threadIdx.x == 0) {
        float ts = 0.f, ts2 = 0.f;
        #pragma unroll
        for (int i = 0; i < 32; i++) { ts += ss[i]; ts2 += ss2[i]; }
        float mean = ts / (float)GSIZE;
        float var  = ts2 / (float)GSIZE - mean * mean;
        g_mu[g]   = mean;
        g_rstd[g] = rsqrtf(var + GN_EPS);
    }
}

// ---------------------------------------------------------------------------
// 2) Normalize + affine + transpose (B,D,S) -> (B,S,D), bf16 out.
// ---------------------------------------------------------------------------
__global__ __launch_bounds__(256) void norm_transpose(const float* __restrict__ in,
                                                      const float* __restrict__ gamma,
                                                      const float* __restrict__ beta) {
    __shared__ float tile[32][129];
    int b = blockIdx.z, tid = threadIdx.x;
    int d0 = blockIdx.y * 32, s0 = blockIdx.x * 128;
    #pragma unroll
    for (int i = 0; i < 4; i++) {
        int idx = tid + i * 256;
        int d = idx >> 5, s4 = idx & 31;
        int gd = d0 + d;
        float4 f = *(const float4*)(in + ((size_t)b * EMB + gd) * S_LEN + s0 + s4 * 4);
        int grp = b * GROUPS + (gd >> 4);
        float sc = g_rstd[grp] * gamma[gd];
        float sh = beta[gd] - g_mu[grp] * sc;
        tile[d][s4 * 4 + 0] = f.x * sc + sh;
        tile[d][s4 * 4 + 1] = f.y * sc + sh;
        tile[d][s4 * 4 + 2] = f.z * sc + sh;
        tile[d][s4 * 4 + 3] = f.w * sc + sh;
    }
    __syncthreads();
    #pragma unroll
    for (int k = 0; k < 2; k++) {
        int u = tid + k * 256;
        int s = u >> 2, c8 = (u & 3) * 8;
        uint32_t r[4];
        #pragma unroll
        for (int e = 0; e < 4; e++)
            r[e] = packbf(tile[c8 + 2 * e][s], tile[c8 + 2 * e + 1][s]);
        *(uint4*)(g_xh + ((size_t)b * S_LEN + s0 + s) * EMB + d0 + c8) = *(uint4*)r;
    }
}

// ---------------------------------------------------------------------------
// 2b) Weight conversion fp32 -> bf16
// ---------------------------------------------------------------------------
__global__ void wconv(const float* __restrict__ w0, const float* __restrict__ w1,
                      const float* __restrict__ w2, const float* __restrict__ w3) {
    const float* src = (blockIdx.y == 0) ? w0 : (blockIdx.y == 1) ? w1
                     : (blockIdx.y == 2) ? w2 : w3;
    __nv_bfloat16* dst = g_wh + (size_t)blockIdx.y * EMB * EMB;
    int i = blockIdx.x * 256 + threadIdx.x;
    float4 f = ((const float4*)src)[i];
    *(uint32_t*)(dst + (size_t)i * 4)     = packbf(f.x, f.y);
    *(uint32_t*)(dst + (size_t)i * 4 + 2) = packbf(f.z, f.w);
}

// ---------------------------------------------------------------------------
// 3) bf16 GEMM: tile 128x128x32, 256 threads (4m x 2n warps, warp 32x64),
//    2-stage cp.async ring, one sync per k-iter, 2 CTAs/SM.
// ---------------------------------------------------------------------------
#define GBM 128
#define GBN 128
#define GBK 32
#define GPAD 40
#define STAGE_BF ((GBM + GBN) * GPAD)      // 10240 bf16 = 20480 B
#define NKS (EMB / GBK)                    // 16
#define SMEM_BYTES 40960                   // 2 stages (static, < 48 KB)

__device__ __forceinline__ void g_load_stage(const __nv_bfloat16* A, const __nv_bfloat16* Wb,
                                             int m0, int k0, __nv_bfloat16* S, int tid) {
    __nv_bfloat16* As = S;
    __nv_bfloat16* Bs = S + GBM * GPAD;
    #pragma unroll
    for (int i = 0; i < 2; i++) {
        int idx = tid + i * 256;
        int r = idx >> 2, q = idx & 3;
        cpasync16(As + r * GPAD + q * 8, A + (size_t)(m0 + r) * EMB + k0 + q * 8);
    }
    #pragma unroll
    for (int i = 0; i < 2; i++) {
        int idx = tid + i * 256;
        int r = idx >> 2, q = idx & 3;
        cpasync16(Bs + r * GPAD + q * 8, Wb + (size_t)r * EMB + k0 + q * 8);
    }
}

// acc[mi][ni]: mi = 2 x 16-row tiles (warp m=32), ni = 8 x 8-col tiles (warp n=64)
__device__ __forceinline__ void g_mainloop(const __nv_bfloat16* A, const __nv_bfloat16* Wb,
                                           int m0, float acc[2][8][4],
                                           char* smem_raw, int tid) {
    __nv_bfloat16* S0 = (__nv_bfloat16*)smem_raw;
    int w = tid >> 5, l = tid & 31;
    int wm = w & 3, wn = w >> 2;
    int lrow = l & 15, lcol = (l >> 4) * 8;

    g_load_stage(A, Wb, m0, 0, S0, tid);
    CP_COMMIT();

    for (int ks = 0; ks < NKS; ks++) {
        if (ks == 0) { CP_WAIT(0); } else { CP_WAIT(1); }
        __syncthreads();
        if (ks + 1 < NKS) {
            g_load_stage(A, Wb, m0, (ks + 1) * GBK, S0 + ((ks + 1) & 1) * STAGE_BF, tid);
            CP_COMMIT();
        }
        __nv_bfloat16* Sc = S0 + (ks & 1) * STAGE_BF;
        __nv_bfloat16* As = Sc;
        __nv_bfloat16* Bs = Sc + GBM * GPAD;
        #pragma unroll
        for (int kk = 0; kk < 2; kk++) {
            uint32_t af[2][4], bt[4][4];
            #pragma unroll
            for (int mi = 0; mi < 2; mi++)
                ldsm4(af[mi], As + (wm * 32 + mi * 16 + lrow) * GPAD + kk * 16 + lcol);
            #pragma unroll
            for (int t = 0; t < 4; t++)
                ldsm4(bt[t], Bs + (wn * 64 + t * 16 + lrow) * GPAD + kk * 16 + lcol);
            #pragma unroll
            for (int mi = 0; mi < 2; mi++)
                #pragma unroll
                for (int t = 0; t < 4; t++) {
                    mma16816(acc[mi][2 * t + 0], af[mi], bt[t][0], bt[t][2]);
                    mma16816(acc[mi][2 * t + 1], af[mi], bt[t][1], bt[t][3]);
                }
        }
        // no end-of-iter sync: next iter's top barrier protects buffer reuse
    }
}

// Fused Q/K/V projection. Epilogue stages the 128x128 C-tile in smem, then
// writes fully-coalesced uint4 stores (two heads' [s,64] slabs per block).
__global__ __launch_bounds__(256, 2) void gemm_qkv(const float* __restrict__ bq,
                                                   const float* __restrict__ bk,
                                                   const float* __restrict__ bv) {
    __shared__ __align__(16) char smem_raw[SMEM_BYTES];
    int tid = threadIdx.x, w = tid >> 5, l = tid & 31;
    int wm = w & 3, wn = w >> 2;
    int lr = l >> 2, cq = (l & 3) * 2;
    int n0g = blockIdx.x * GBN;          // 0..1408
    int mode = n0g >> 9;                 // 0=q 1=k 2=v
    int n0 = n0g & 511;
    int m0 = blockIdx.y * GBM;
    const float* bias = (mode == 0) ? bq : (mode == 1) ? bk : bv;

    float acc[2][8][4] = {};
    g_mainloop(g_xh, g_wh + (size_t)n0g * EMB, m0, acc, smem_raw, tid);

    int b   = m0 >> 12;
    int sm0 = m0 & 4095;

    __nv_bfloat16* dst = (mode == 0) ? g_qh : (mode == 1) ? g_kh : g_vh;
    const float sc = (mode == 0) ? QSCALE : 1.0f;

    __syncthreads();   // smem reuse after mainloop
    __nv_bfloat16* Tb = (__nv_bfloat16*)smem_raw;      // [128][136] bf16 = 34.8 KB
    #pragma unroll
    for (int mi = 0; mi < 2; mi++) {
        int rl = wm * 32 + mi * 16 + lr;
        #pragma unroll
        for (int ni = 0; ni < 8; ni++) {
            int cl = wn * 64 + ni * 8 + cq;
            float b0 = bias[n0 + cl], b1 = bias[n0 + cl + 1];
            *(uint32_t*)(Tb + rl * 136 + cl) =
                packbf((acc[mi][ni][0] + b0) * sc, (acc[mi][ni][1] + b1) * sc);
            *(uint32_t*)(Tb + (rl + 8) * 136 + cl) =
                packbf((acc[mi][ni][2] + b0) * sc, (acc[mi][ni][3] + b1) * sc);
        }
    }
    __syncthreads();
    int h0 = n0 >> 6;                                  // block covers heads h0, h0+1
    #pragma unroll
    for (int i = 0; i < 8; i++) {
        int idx = tid + i * 256;
        int row = idx >> 4, u = idx & 15;
        int h = h0 + (u >> 3), d8 = (u & 7) * 8;
        size_t hb = (size_t)(b * HEADS + h) * S_LEN;
        *(uint4*)(dst + (hb + sm0 + row) * DH + d8) = *(uint4*)(Tb + row * 136 + u * 8);
    }
}

// Output projection + residual, fp32 [B,D,S] out. Two 64-col transpose passes,
// buffer [64 cols][132 rows] fp32 = 33.8 KB (row stride 528 B, 16B-aligned).
__global__ __launch_bounds__(256, 2) void gemm_out(const float* __restrict__ bias,
                                                   float* __restrict__ dout,
                                                   const float* __restrict__ residual) {
    __shared__ __align__(16) char smem_raw[SMEM_BYTES];
    int tid = threadIdx.x, w = tid >> 5, l = tid & 31;
    int wm = w & 3, wn = w >> 2;
    int lr = l >> 2, cq = (l & 3) * 2;
    int n0 = blockIdx.x * GBN;
    int m0 = blockIdx.y * GBM;

    float acc[2][8][4] = {};
    g_mainloop(g_oh, g_wh + (size_t)3 * EMB * EMB + (size_t)n0 * EMB, m0, acc, smem_raw, tid);

    int b   = m0 >> 12;
    int sm0 = m0 & 4095;

    float* Tf = (float*)smem_raw;                      // [64][132] fp32
    #pragma unroll
    for (int p = 0; p < 2; p++) {
        __syncthreads();
        if (wn == p) {
            #pragma unroll
            for (int mi = 0; mi < 2; mi++) {
                int rl = wm * 32 + mi * 16 + lr;       // 0..127
                #pragma unroll
                for (int ni = 0; ni < 8; ni++) {
                    int cl = ni * 8 + cq;              // 0..63 within half
                    float b0 = bias[n0 + p * 64 + cl], b1 = bias[n0 + p * 64 + cl + 1];
                    Tf[cl * 132 + rl]           = acc[mi][ni][0] + b0;
                    Tf[(cl + 1) * 132 + rl]     = acc[mi][ni][1] + b1;
                    Tf[cl * 132 + rl + 8]       = acc[mi][ni][2] + b0;
                    Tf[(cl + 1) * 132 + rl + 8] = acc[mi][ni][3] + b1;
                }
            }
        }
        __syncthreads();
        #pragma unroll
        for (int i = 0; i < 8; i++) {
            int idx = tid + i * 256;
            int dd = idx >> 5, ch = idx & 31;          // dd 0..63, ch 0..31
            float4 v = *(float4*)(Tf + dd * 132 + ch * 4);
            size_t oi = ((size_t)b * EMB + n0 + p * 64 + dd) * S_LEN + sm0 + ch * 4;
            float4 r = *(const float4*)(residual + oi);
            v.x += r.x; v.y += r.y; v.z += r.z; v.w += r.w;
            *(float4*)(dout + oi) = v;
        }
    }
}

// ---------------------------------------------------------------------------
// 4a) Linear attention: partial M^T = (K^T V)^T, Ksum, Vsum per (head, chunk).
// ---------------------------------------------------------------------------
__global__ __launch_bounds__(256) void m_partial() {
    __shared__ float Kf[128][64];                 // 32 KB
    __shared__ __nv_bfloat16 Vs[128][64];         // 16 KB
    int tid = threadIdx.x;
    int chunk = blockIdx.x, bh = blockIdx.y;
    const __nv_bfloat16* Kb = g_kh + ((size_t)bh * S_LEN + chunk * 128) * DH;
    const __nv_bfloat16* Vb = g_vh + ((size_t)bh * S_LEN + chunk * 128) * DH;
    #pragma unroll
    for (int i = 0; i < 4; i++) {
        int idx = tid + i * 256;
        int r = idx >> 3, q = idx & 7;
        uint4 u = *(const uint4*)(Kb + (size_t)r * DH + q * 8);
        uint32_t ws[4] = {u.x, u.y, u.z, u.w};
        #pragma unroll
        for (int e = 0; e < 4; e++) {
            Kf[r][q * 8 + 2 * e]     = bflo(ws[e]);
            Kf[r][q * 8 + 2 * e + 1] = bfhi(ws[e]);
        }
        *(uint4*)(&Vs[r][q * 8]) = *(const uint4*)(Vb + (size_t)r * DH + q * 8);
    }
    __syncthreads();

    int ti = tid & 15, tj = tid >> 4;
    int i0 = ti * 4, j0 = tj * 4;
    float acc[4][4] = {};
    #pragma unroll 4
    for (int s = 0; s < 128; s++) {
        float4 kf = *(float4*)(&Kf[s][i0]);
        uint2 vv = *(uint2*)(&Vs[s][j0]);
        float vf[4] = {bflo(vv.x), bfhi(vv.x), bflo(vv.y), bfhi(vv.y)};
        #pragma unroll
        for (int a = 0; a < 4; a++) {
            acc[a][0] += vf[a] * kf.x;
            acc[a][1] += vf[a] * kf.y;
            acc[a][2] += vf[a] * kf.z;
            acc[a][3] += vf[a] * kf.w;
        }
    }
    float* mp = g_mp + (size_t)(bh * MPCH + chunk) * MPSZ;
    #pragma unroll
    for (int a = 0; a < 4; a++)
        #pragma unroll
        for (int bb = 0; bb < 4; bb++)
            mp[(j0 + a) * 64 + i0 + bb] = acc[a][bb];     // Mt[j][i]

    if (tid < 64) {
        float s = 0.f;
        for (int r = 0; r < 128; r++) s += Kf[r][tid];
        mp[4096 + tid] = s;                               // Ksum
    } else if (tid < 128) {
        int j = tid - 64;
        float s = 0.f;
        for (int r = 0; r < 128; r++) {
            uint32_t u = (uint32_t)(*(const uint16_t*)&Vs[r][j]);
            s += __uint_as_float(u << 16);
        }
        mp[4160 + j] = s;                                 // Vsum
    }
}

// 4b) Reduce partials -> g_mtb (bf16), g_ks, g_vs.
__global__ void m_reduce() {
    int bh = blockIdx.x, tid = threadIdx.x;
    for (int e = tid; e < MPSZ; e += 256) {
        float s = 0.f;
        #pragma unroll 8
        for (int c = 0; c < MPCH; c++)
            s += g_mp[(size_t)(bh * MPCH + c) * MPSZ + e];
        if (e < 4096)      g_mtb[bh * 4096 + e] = __float2bfloat16(s);
        else if (e < 4160) g_ks[bh * 64 + e - 4096] = s;
        else               g_vs[bh * 64 + e - 4160] = s;
    }
}

// 4c) O = (Vsum + Q M) / (4096 + Q Ksum).
__global__ __launch_bounds__(128) void attn_lin() {
    __shared__ __align__(16) __nv_bfloat16 Mts[64 * 72];
    __shared__ float ks[64], vs[64];
    int tid = threadIdx.x, w = tid >> 5, l = tid & 31;
    int qt = blockIdx.x, bh = blockIdx.y;

    #pragma unroll
    for (int i = 0; i < 4; i++) {
        int idx = tid + i * 128;
        int r = idx >> 3, q = idx & 7;
        *(uint4*)(Mts + r * 72 + q * 8) = *(const uint4*)(g_mtb + bh * 4096 + r * 64 + q * 8);
    }
    if (tid < 64) ks[tid] = g_ks[bh * 64 + tid];
    else vs[tid - 64] = g_vs[bh * 64 + tid - 64];
    __syncthreads();

    const __nv_bfloat16* Qb = g_qh + (size_t)bh * S_LEN * DH;
    int cq = (l & 3) * 2;
    int rq = qt * 128 + w * 32 + (l >> 2);
    uint32_t qf[2][4][4];
    #pragma unroll
    for (int mi = 0; mi < 2; mi++) {
        int rr = rq + mi * 16;
        #pragma unroll
        for (int kk = 0; kk < 4; kk++) {
            int c = kk * 16 + cq;
            qf[mi][kk][0] = *(const uint32_t*)(Qb + (size_t)rr * DH + c);
            qf[mi][kk][1] = *(const uint32_t*)(Qb + (size_t)(rr + 8) * DH + c);
            qf[mi][kk][2] = *(const uint32_t*)(Qb + (size_t)rr * DH + c + 8);
            qf[mi][kk][3] = *(const uint32_t*)(Qb + (size_t)(rr + 8) * DH + c + 8);
        }
    }

    float oacc[2][8][4] = {};
    int lrow = l & 15, lcol = (l >> 4) * 8;
    #pragma unroll
    for (int kk = 0; kk < 4; kk++) {
        uint32_t bt[4][4];
        #pragma unroll
        for (int rg = 0; rg < 4; rg++)
            ldsm4(bt[rg], Mts + (rg * 16 + lrow) * 72 + kk * 16 + lcol);
        #pragma unroll
        for (int mi = 0; mi < 2; mi++)
            #pragma unroll
            for (int rg = 0; rg < 4; rg++) {
                mma16816(oacc[mi][2 * rg + 0], qf[mi][kk], bt[rg][0], bt[rg][2]);
                mma16816(oacc[mi][2 * rg + 1], qf[mi][kk], bt[rg][1], bt[rg][3]);
            }
    }

    int b = bh >> 3, h = bh & 7;
    #pragma unroll
    for (int mi = 0; mi < 2; mi++) {
        float p0 = 0.f, p1 = 0.f;
        #pragma unroll
        for (int kk = 0; kk < 4; kk++) {
            int c = kk * 16 + cq;
            uint32_t u0 = qf[mi][kk][0], u1 = qf[mi][kk][1];
            uint32_t u2 = qf[mi][kk][2], u3 = qf[mi][kk][3];
            p0 += bflo(u0) * ks[c]     + bfhi(u0) * ks[c + 1];
            p0 += bflo(u2) * ks[c + 8] + bfhi(u2) * ks[c + 9];
            p1 += bflo(u1) * ks[c]     + bfhi(u1) * ks[c + 1];
            p1 += bflo(u3) * ks[c + 8] + bfhi(u3) * ks[c + 9];
        }
        p0 += __shfl_xor_sync(0xffffffffu, p0, 1);
        p0 += __shfl_xor_sync(0xffffffffu, p0, 2);
        p1 += __shfl_xor_sync(0xffffffffu, p1, 1);
        p1 += __shfl_xor_sync(0xffffffffu, p1, 2);
        float i0 = 1.f / ((float)S_LEN + p0), i1 = 1.f / ((float)S_LEN + p1);
        int rr = rq + mi * 16;
        #pragma unroll
        for (int j = 0; j < 8; j++) {
            int col = j * 8 + cq;
            float a0 = (vs[col] + oacc[mi][j][0]) * i0;
            float a1 = (vs[col + 1] + oacc[mi][j][1]) * i0;
            float a2 = (vs[col] + oacc[mi][j][2]) * i1;
            float a3 = (vs[col + 1] + oacc[mi][j][3]) * i1;
            *(uint32_t*)(g_oh + ((size_t)(b * S_LEN + rr)) * EMB + h * DH + col) =
                packbf(a0, a1);
            *(uint32_t*)(g_oh + ((size_t)(b * S_LEN + rr + 8)) * EMB + h * DH + col) =
                packbf(a2, a3);
        }
    }
}

// ---------------------------------------------------------------------------
// Launch
// ---------------------------------------------------------------------------
extern "C" void kernel_launch(void* const* d_in, const int* in_sizes, int n_in,
                              void* d_out, int out_size) {
    const float* input = (const float*)d_in[0];
    const float* gamma = (const float*)d_in[1];
    const float* beta  = (const float*)d_in[2];
    const float* wq = (const float*)d_in[3];
    const float* bq = (const float*)d_in[4];
    const float* wk = (const float*)d_in[5];
    const float* bk = (const float*)d_in[6];
    const float* wv = (const float*)d_in[7];
    const float* bv = (const float*)d_in[8];
    const float* wo = (const float*)d_in[9];
    const float* bo = (const float*)d_in[10];
    float* out = (float*)d_out;

    gn_stats<<<BATCH * GROUPS, 1024>>>(input);
    wconv<<<dim3(256, 4), 256>>>(wq, wk, wv, wo);
    norm_transpose<<<dim3(S_LEN / 128, EMB / 32, BATCH), 256>>>(input, gamma, beta);

    gemm_qkv<<<dim3(3 * EMB / GBN, (BATCH * S_LEN) / GBM), 256>>>(bq, bk, bv);

    m_partial<<<dim3(MPCH, NBH), 256>>>();
    m_reduce<<<NBH, 256>>>();
    attn_lin<<<dim3(S_LEN / 128, NBH), 128>>>();

    gemm_out<<<dim3(EMB / GBN, (BATCH * S_LEN) / GBM), 256>>>(bo, out, input);
}

// round 14
// speedup vs baseline: 1.0054x; 1.0052x over previous
#include <cuda_runtime.h>
#include <cuda_bf16.h>
#include <cstdint>

// Problem constants
#define S_LEN  4096
#define EMB    512
#define HEADS  8
#define DH     64
#define BATCH  2
#define GROUPS 32
#define GSIZE  65536
#define GN_EPS 100000.0f
#define QSCALE 0.125f   // 1/sqrt(64)

// Scratch (device globals; allocation-free rule)
__device__ __nv_bfloat16 g_xh[BATCH * S_LEN * EMB];        // normalized input, [b][s][d]
__device__ __nv_bfloat16 g_oh[BATCH * S_LEN * EMB];        // attention out, [b][s][h*64+d]
__device__ __nv_bfloat16 g_wh[4 * EMB * EMB];              // bf16 weights: q,k,v,o concat
__device__ float g_mu[BATCH * GROUPS];
__device__ float g_rstd[BATCH * GROUPS];
__device__ __nv_bfloat16 g_qh[BATCH * HEADS * S_LEN * DH]; // [b][h][s][dh], pre-scaled 1/8
__device__ __nv_bfloat16 g_kh[BATCH * HEADS * S_LEN * DH]; // [b][h][s][dh]
__device__ __nv_bfloat16 g_vh[BATCH * HEADS * S_LEN * DH]; // [b][h][s][dh]
// Linear-attention small matrices
#define NBH (BATCH * HEADS)           // 16
#define MPCH 32                       // 128-seq chunks per head
#define MPSZ 4224                     // 64*64 M + 64 Ksum + 64 Vsum
__device__ float g_mp[NBH * MPCH * MPSZ];          // partials
__device__ __nv_bfloat16 g_mtb[NBH * 64 * 64];     // M^T per head, bf16
__device__ float g_ks[NBH * 64];                   // Ksum
__device__ float g_vs[NBH * 64];                   // Vsum

__device__ __forceinline__ void mma16816(float c[4], const uint32_t a[4],
                                         uint32_t b0, uint32_t b1) {
    asm volatile(
        "mma.sync.aligned.m16n8k16.row.col.f32.bf16.bf16.f32 "
        "{%0,%1,%2,%3},{%4,%5,%6,%7},{%8,%9},{%0,%1,%2,%3};\n"
        : "+f"(c[0]), "+f"(c[1]), "+f"(c[2]), "+f"(c[3])
        : "r"(a[0]), "r"(a[1]), "r"(a[2]), "r"(a[3]), "r"(b0), "r"(b1));
}
__device__ __forceinline__ uint32_t packbf(float x, float y) {
    uint32_t d;
    asm("cvt.rn.bf16x2.f32 %0, %1, %2;" : "=r"(d) : "f"(y), "f"(x));
    return d;
}
__device__ __forceinline__ float bflo(uint32_t u) { return __uint_as_float(u << 16); }
__device__ __forceinline__ float bfhi(uint32_t u) { return __uint_as_float(u & 0xffff0000u); }
__device__ __forceinline__ void ldsm4(uint32_t* r, const __nv_bfloat16* p) {
    uint32_t a = (uint32_t)__cvta_generic_to_shared((void*)p);
    asm volatile("ldmatrix.sync.aligned.m8n8.x4.shared.b16 {%0,%1,%2,%3}, [%4];\n"
        : "=r"(r[0]), "=r"(r[1]), "=r"(r[2]), "=r"(r[3]) : "r"(a));
}
__device__ __forceinline__ void cpasync16(void* smem, const void* gmem) {
    uint32_t s = (uint32_t)__cvta_generic_to_shared(smem);
    asm volatile("cp.async.cg.shared.global [%0], [%1], 16;\n" :: "r"(s), "l"(gmem));
}
#define CP_COMMIT() asm volatile("cp.async.commit_group;\n" ::: "memory")
#define CP_WAIT(N)  asm volatile("cp.async.wait_group %0;\n" :: "n"(N) : "memory")

// ---------------------------------------------------------------------------
// 1) GroupNorm statistics
// ---------------------------------------------------------------------------
__global__ void gn_stats(const float* __restrict__ in) {
    int g = blockIdx.x;
    const float4* p = (const float4*)(in + (size_t)g * GSIZE);
    float s = 0.f, s2 = 0.f;
    for (int i = threadIdx.x; i < GSIZE / 4; i += 1024) {
        float4 f = p[i];
        s  += f.x + f.y + f.z + f.w;
        s2 += f.x * f.x + f.y * f.y + f.z * f.z + f.w * f.w;
    }
    __shared__ float ss[32], ss2[32];
    #pragma unroll
    for (int o = 16; o > 0; o >>= 1) {
        s  += __shfl_down_sync(0xffffffffu, s,  o);
        s2 += __shfl_down_sync(0xffffffffu, s2, o);
    }
    int lane = threadIdx.x & 31, w = threadIdx.x >> 5;
    if (lane == 0) { ss[w] = s; ss2[w] = s2; }
    __syncthreads();
    if (threadIdx.x == 0) {
        float ts = 0.f, ts2 = 0.f;
        #pragma unroll
        for (int i = 0; i < 32; i++) { ts += ss[i]; ts2 += ss2[i]; }
        float mean = ts / (float)GSIZE;
        float var  = ts2 / (float)GSIZE - mean * mean;
        g_mu[g]   = mean;
        g_rstd[g] = rsqrtf(var + GN_EPS);
    }
}

// ---------------------------------------------------------------------------
// 2) Normalize + affine + transpose (B,D,S) -> (B,S,D), bf16 out.
// ---------------------------------------------------------------------------
__global__ __launch_bounds__(256) void norm_transpose(const float* __restrict__ in,
                                                      const float* __restrict__ gamma,
                                                      const float* __restrict__ beta) {
    __shared__ float tile[32][129];
    int b = blockIdx.z, tid = threadIdx.x;
    int d0 = blockIdx.y * 32, s0 = blockIdx.x * 128;
    #pragma unroll
    for (int i = 0; i < 4; i++) {
        int idx = tid + i * 256;
        int d = idx >> 5, s4 = idx & 31;
        int gd = d0 + d;
        float4 f = *(const float4*)(in + ((size_t)b * EMB + gd) * S_LEN + s0 + s4 * 4);
        int grp = b * GROUPS + (gd >> 4);
        float sc = g_rstd[grp] * gamma[gd];
        float sh = beta[gd] - g_mu[grp] * sc;
        tile[d][s4 * 4 + 0] = f.x * sc + sh;
        tile[d][s4 * 4 + 1] = f.y * sc + sh;
        tile[d][s4 * 4 + 2] = f.z * sc + sh;
        tile[d][s4 * 4 + 3] = f.w * sc + sh;
    }
    __syncthreads();
    #pragma unroll
    for (int k = 0; k < 2; k++) {
        int u = tid + k * 256;
        int s = u >> 2, c8 = (u & 3) * 8;
        uint32_t r[4];
        #pragma unroll
        for (int e = 0; e < 4; e++)
            r[e] = packbf(tile[c8 + 2 * e][s], tile[c8 + 2 * e + 1][s]);
        *(uint4*)(g_xh + ((size_t)b * S_LEN + s0 + s) * EMB + d0 + c8) = *(uint4*)r;
    }
}

// ---------------------------------------------------------------------------
// 2b) Weight conversion fp32 -> bf16
// ---------------------------------------------------------------------------
__global__ void wconv(const float* __restrict__ w0, const float* __restrict__ w1,
                      const float* __restrict__ w2, const float* __restrict__ w3) {
    const float* src = (blockIdx.y == 0) ? w0 : (blockIdx.y == 1) ? w1
                     : (blockIdx.y == 2) ? w2 : w3;
    __nv_bfloat16* dst = g_wh + (size_t)blockIdx.y * EMB * EMB;
    int i = blockIdx.x * 256 + threadIdx.x;
    float4 f = ((const float4*)src)[i];
    *(uint32_t*)(dst + (size_t)i * 4)     = packbf(f.x, f.y);
    *(uint32_t*)(dst + (size_t)i * 4 + 2) = packbf(f.z, f.w);
}

// ---------------------------------------------------------------------------
// 3) bf16 GEMM: tile 128x128x32, 256 threads (4m x 2n warps, warp 32x64),
//    2-stage cp.async ring, one sync per k-iter, 2 CTAs/SM.
// ---------------------------------------------------------------------------
#define GBM 128
#define GBN 128
#define GBK 32
#define GPAD 40
#define STAGE_BF ((GBM + GBN) * GPAD)      // 10240 bf16 = 20480 B
#define NKS (EMB / GBK)                    // 16
#define SMEM_BYTES 40960                   // 2 stages (static, < 48 KB)

__device__ __forceinline__ void g_load_stage(const __nv_bfloat16* A, const __nv_bfloat16* Wb,
                                             int m0, int k0, __nv_bfloat16* S, int tid) {
    __nv_bfloat16* As = S;
    __nv_bfloat16* Bs = S + GBM * GPAD;
    #pragma unroll
    for (int i = 0; i < 2; i++) {
        int idx = tid + i * 256;
        int r = idx >> 2, q = idx & 3;
        cpasync16(As + r * GPAD + q * 8, A + (size_t)(m0 + r) * EMB + k0 + q * 8);
    }
    #pragma unroll
    for (int i = 0; i < 2; i++) {
        int idx = tid + i * 256;
        int r = idx >> 2, q = idx & 3;
        cpasync16(Bs + r * GPAD + q * 8, Wb + (size_t)r * EMB + k0 + q * 8);
    }
}

// acc[mi][ni]: mi = 2 x 16-row tiles (warp m=32), ni = 8 x 8-col tiles (warp n=64)
__device__ __forceinline__ void g_mainloop(const __nv_bfloat16* A, const __nv_bfloat16* Wb,
                                           int m0, float acc[2][8][4],
                                           char* smem_raw, int tid) {
    __nv_bfloat16* S0 = (__nv_bfloat16*)smem_raw;
    int w = tid >> 5, l = tid & 31;
    int wm = w & 3, wn = w >> 2;
    int lrow = l & 15, lcol = (l >> 4) * 8;

    g_load_stage(A, Wb, m0, 0, S0, tid);
    CP_COMMIT();

    for (int ks = 0; ks < NKS; ks++) {
        if (ks == 0) { CP_WAIT(0); } else { CP_WAIT(1); }
        __syncthreads();
        if (ks + 1 < NKS) {
            g_load_stage(A, Wb, m0, (ks + 1) * GBK, S0 + ((ks + 1) & 1) * STAGE_BF, tid);
            CP_COMMIT();
        }
        __nv_bfloat16* Sc = S0 + (ks & 1) * STAGE_BF;
        __nv_bfloat16* As = Sc;
        __nv_bfloat16* Bs = Sc + GBM * GPAD;
        #pragma unroll
        for (int kk = 0; kk < 2; kk++) {
            uint32_t af[2][4], bt[4][4];
            #pragma unroll
            for (int mi = 0; mi < 2; mi++)
                ldsm4(af[mi], As + (wm * 32 + mi * 16 + lrow) * GPAD + kk * 16 + lcol);
            #pragma unroll
            for (int t = 0; t < 4; t++)
                ldsm4(bt[t], Bs + (wn * 64 + t * 16 + lrow) * GPAD + kk * 16 + lcol);
            #pragma unroll
            for (int mi = 0; mi < 2; mi++)
                #pragma unroll
                for (int t = 0; t < 4; t++) {
                    mma16816(acc[mi][2 * t + 0], af[mi], bt[t][0], bt[t][2]);
                    mma16816(acc[mi][2 * t + 1], af[mi], bt[t][1], bt[t][3]);
                }
        }
        // no end-of-iter sync: next iter's top barrier protects buffer reuse
    }
}

// Fused Q/K/V projection. Epilogue stages the 128x128 C-tile in smem, then
// writes fully-coalesced uint4 stores (two heads' [s,64] slabs per block).
__global__ __launch_bounds__(256, 2) void gemm_qkv(const float* __restrict__ bq,
                                                   const float* __restrict__ bk,
                                                   const float* __restrict__ bv) {
    __shared__ __align__(16) char smem_raw[SMEM_BYTES];
    int tid = threadIdx.x, w = tid >> 5, l = tid & 31;
    int wm = w & 3, wn = w >> 2;
    int lr = l >> 2, cq = (l & 3) * 2;
    int n0g = blockIdx.x * GBN;          // 0..1408
    int mode = n0g >> 9;                 // 0=q 1=k 2=v
    int n0 = n0g & 511;
    int m0 = blockIdx.y * GBM;
    const float* bias = (mode == 0) ? bq : (mode == 1) ? bk : bv;

    float acc[2][8][4] = {};
    g_mainloop(g_xh, g_wh + (size_t)n0g * EMB, m0, acc, smem_raw, tid);

    int b   = m0 >> 12;
    int sm0 = m0 & 4095;

    __nv_bfloat16* dst = (mode == 0) ? g_qh : (mode == 1) ? g_kh : g_vh;
    const float sc = (mode == 0) ? QSCALE : 1.0f;

    __syncthreads();   // smem reuse after mainloop
    __nv_bfloat16* Tb = (__nv_bfloat16*)smem_raw;      // [128][136] bf16 = 34.8 KB
    #pragma unroll
    for (int mi = 0; mi < 2; mi++) {
        int rl = wm * 32 + mi * 16 + lr;
        #pragma unroll
        for (int ni = 0; ni < 8; ni++) {
            int cl = wn * 64 + ni * 8 + cq;
            float b0 = bias[n0 + cl], b1 = bias[n0 + cl + 1];
            *(uint32_t*)(Tb + rl * 136 + cl) =
                packbf((acc[mi][ni][0] + b0) * sc, (acc[mi][ni][1] + b1) * sc);
            *(uint32_t*)(Tb + (rl + 8) * 136 + cl) =
                packbf((acc[mi][ni][2] + b0) * sc, (acc[mi][ni][3] + b1) * sc);
        }
    }
    __syncthreads();
    int h0 = n0 >> 6;                                  // block covers heads h0, h0+1
    #pragma unroll
    for (int i = 0; i < 8; i++) {
        int idx = tid + i * 256;
        int row = idx >> 4, u = idx & 15;
        int h = h0 + (u >> 3), d8 = (u & 7) * 8;
        size_t hb = (size_t)(b * HEADS + h) * S_LEN;
        *(uint4*)(dst + (hb + sm0 + row) * DH + d8) = *(uint4*)(Tb + row * 136 + u * 8);
    }
}

// Output projection + residual, fp32 [B,D,S] out. Two 64-col transpose passes,
// buffer [64 cols][132 rows] fp32 = 33.8 KB (row stride 528 B, 16B-aligned).
__global__ __launch_bounds__(256, 2) void gemm_out(const float* __restrict__ bias,
                                                   float* __restrict__ dout,
                                                   const float* __restrict__ residual) {
    __shared__ __align__(16) char smem_raw[SMEM_BYTES];
    int tid = threadIdx.x, w = tid >> 5, l = tid & 31;
    int wm = w & 3, wn = w >> 2;
    int lr = l >> 2, cq = (l & 3) * 2;
    int n0 = blockIdx.x * GBN;
    int m0 = blockIdx.y * GBM;

    float acc[2][8][4] = {};
    g_mainloop(g_oh, g_wh + (size_t)3 * EMB * EMB + (size_t)n0 * EMB, m0, acc, smem_raw, tid);

    int b   = m0 >> 12;
    int sm0 = m0 & 4095;

    float* Tf = (float*)smem_raw;                      // [64][132] fp32
    #pragma unroll
    for (int p = 0; p < 2; p++) {
        __syncthreads();
        if (wn == p) {
            #pragma unroll
            for (int mi = 0; mi < 2; mi++) {
                int rl = wm * 32 + mi * 16 + lr;       // 0..127
                #pragma unroll
                for (int ni = 0; ni < 8; ni++) {
                    int cl = ni * 8 + cq;              // 0..63 within half
                    float b0 = bias[n0 + p * 64 + cl], b1 = bias[n0 + p * 64 + cl + 1];
                    Tf[cl * 132 + rl]           = acc[mi][ni][0] + b0;
                    Tf[(cl + 1) * 132 + rl]     = acc[mi][ni][1] + b1;
                    Tf[cl * 132 + rl + 8]       = acc[mi][ni][2] + b0;
                    Tf[(cl + 1) * 132 + rl + 8] = acc[mi][ni][3] + b1;
                }
            }
        }
        __syncthreads();
        #pragma unroll
        for (int i = 0; i < 8; i++) {
            int idx = tid + i * 256;
            int dd = idx >> 5, ch = idx & 31;          // dd 0..63, ch 0..31
            float4 v = *(float4*)(Tf + dd * 132 + ch * 4);
            size_t oi = ((size_t)b * EMB + n0 + p * 64 + dd) * S_LEN + sm0 + ch * 4;
            float4 r = *(const float4*)(residual + oi);
            v.x += r.x; v.y += r.y; v.z += r.z; v.w += r.w;
            *(float4*)(dout + oi) = v;
        }
    }
}

// ---------------------------------------------------------------------------
// 4a) Linear attention: partial M^T = (K^T V)^T, Ksum, Vsum per (head, chunk).
// ---------------------------------------------------------------------------
__global__ __launch_bounds__(256) void m_partial() {
    __shared__ float Kf[128][64];                 // 32 KB
    __shared__ __nv_bfloat16 Vs[128][64];         // 16 KB
    int tid = threadIdx.x;
    int chunk = blockIdx.x, bh = blockIdx.y;
    const __nv_bfloat16* Kb = g_kh + ((size_t)bh * S_LEN + chunk * 128) * DH;
    const __nv_bfloat16* Vb = g_vh + ((size_t)bh * S_LEN + chunk * 128) * DH;
    #pragma unroll
    for (int i = 0; i < 4; i++) {
        int idx = tid + i * 256;
        int r = idx >> 3, q = idx & 7;
        uint4 u = *(const uint4*)(Kb + (size_t)r * DH + q * 8);
        uint32_t ws[4] = {u.x, u.y, u.z, u.w};
        #pragma unroll
        for (int e = 0; e < 4; e++) {
            Kf[r][q * 8 + 2 * e]     = bflo(ws[e]);
            Kf[r][q * 8 + 2 * e + 1] = bfhi(ws[e]);
        }
        *(uint4*)(&Vs[r][q * 8]) = *(const uint4*)(Vb + (size_t)r * DH + q * 8);
    }
    __syncthreads();

    int ti = tid & 15, tj = tid >> 4;
    int i0 = ti * 4, j0 = tj * 4;
    float acc[4][4] = {};
    #pragma unroll 4
    for (int s = 0; s < 128; s++) {
        float4 kf = *(float4*)(&Kf[s][i0]);
        uint2 vv = *(uint2*)(&Vs[s][j0]);
        float vf[4] = {bflo(vv.x), bfhi(vv.x), bflo(vv.y), bfhi(vv.y)};
        #pragma unroll
        for (int a = 0; a < 4; a++) {
            acc[a][0] += vf[a] * kf.x;
            acc[a][1] += vf[a] * kf.y;
            acc[a][2] += vf[a] * kf.z;
            acc[a][3] += vf[a] * kf.w;
        }
    }
    float* mp = g_mp + (size_t)(bh * MPCH + chunk) * MPSZ;
    #pragma unroll
    for (int a = 0; a < 4; a++)
        #pragma unroll
        for (int bb = 0; bb < 4; bb++)
            mp[(j0 + a) * 64 + i0 + bb] = acc[a][bb];     // Mt[j][i]

    if (tid < 64) {
        float s = 0.f;
        for (int r = 0; r < 128; r++) s += Kf[r][tid];
        mp[4096 + tid] = s;                               // Ksum
    } else if (tid < 128) {
        int j = tid - 64;
        float s = 0.f;
        for (int r = 0; r < 128; r++) {
            uint32_t u = (uint32_t)(*(const uint16_t*)&Vs[r][j]);
            s += __uint_as_float(u << 16);
        }
        mp[4160 + j] = s;                                 // Vsum
    }
}

// 4b) Reduce partials -> g_mtb (bf16), g_ks, g_vs.
__global__ void m_reduce() {
    int bh = blockIdx.x, tid = threadIdx.x;
    for (int e = tid; e < MPSZ; e += 256) {
        float s = 0.f;
        #pragma unroll 8
        for (int c = 0; c < MPCH; c++)
            s += g_mp[(size_t)(bh * MPCH + c) * MPSZ + e];
        if (e < 4096)      g_mtb[bh * 4096 + e] = __float2bfloat16(s);
        else if (e < 4160) g_ks[bh * 64 + e - 4096] = s;
        else               g_vs[bh * 64 + e - 4160] = s;
    }
}

// 4c) O = (Vsum + Q M) / (4096 + Q Ksum).
__global__ __launch_bounds__(128) void attn_lin() {
    __shared__ __align__(16) __nv_bfloat16 Mts[64 * 72];
    __shared__ float ks[64], vs[64];
    int tid = threadIdx.x, w = tid >> 5, l = tid & 31;
    int qt = blockIdx.x, bh = blockIdx.y;

    #pragma unroll
    for (int i = 0; i < 4; i++) {
        int idx = tid + i * 128;
        int r = idx >> 3, q = idx & 7;
        *(uint4*)(Mts + r * 72 + q * 8) = *(const uint4*)(g_mtb + bh * 4096 + r * 64 + q * 8);
    }
    if (tid < 64) ks[tid] = g_ks[bh * 64 + tid];
    else vs[tid - 64] = g_vs[bh * 64 + tid - 64];
    __syncthreads();

    const __nv_bfloat16* Qb = g_qh + (size_t)bh * S_LEN * DH;
    int cq = (l & 3) * 2;
    int rq = qt * 128 + w * 32 + (l >> 2);
    uint32_t qf[2][4][4];
    #pragma unroll
    for (int mi = 0; mi < 2; mi++) {
        int rr = rq + mi * 16;
        #pragma unroll
        for (int kk = 0; kk < 4; kk++) {
            int c = kk * 16 + cq;
            qf[mi][kk][0] = *(const uint32_t*)(Qb + (size_t)rr * DH + c);
            qf[mi][kk][1] = *(const uint32_t*)(Qb + (size_t)(rr + 8) * DH + c);
            qf[mi][kk][2] = *(const uint32_t*)(Qb + (size_t)rr * DH + c + 8);
            qf[mi][kk][3] = *(const uint32_t*)(Qb + (size_t)(rr + 8) * DH + c + 8);
        }
    }

    float oacc[2][8][4] = {};
    int lrow = l & 15, lcol = (l >> 4) * 8;
    #pragma unroll
    for (int kk = 0; kk < 4; kk++) {
        uint32_t bt[4][4];
        #pragma unroll
        for (int rg = 0; rg < 4; rg++)
            ldsm4(bt[rg], Mts + (rg * 16 + lrow) * 72 + kk * 16 + lcol);
        #pragma unroll
        for (int mi = 0; mi < 2; mi++)
            #pragma unroll
            for (int rg = 0; rg < 4; rg++) {
                mma16816(oacc[mi][2 * rg + 0], qf[mi][kk], bt[rg][0], bt[rg][2]);
                mma16816(oacc[mi][2 * rg + 1], qf[mi][kk], bt[rg][1], bt[rg][3]);
            }
    }

    int b = bh >> 3, h = bh & 7;
    #pragma unroll
    for (int mi = 0; mi < 2; mi++) {
        float p0 = 0.f, p1 = 0.f;
        #pragma unroll
        for (int kk = 0; kk < 4; kk++) {
            int c = kk * 16 + cq;
            uint32_t u0 = qf[mi][kk][0], u1 = qf[mi][kk][1];
            uint32_t u2 = qf[mi][kk][2], u3 = qf[mi][kk][3];
            p0 += bflo(u0) * ks[c]     + bfhi(u0) * ks[c + 1];
            p0 += bflo(u2) * ks[c + 8] + bfhi(u2) * ks[c + 9];
            p1 += bflo(u1) * ks[c]     + bfhi(u1) * ks[c + 1];
            p1 += bflo(u3) * ks[c + 8] + bfhi(u3) * ks[c + 9];
        }
        p0 += __shfl_xor_sync(0xffffffffu, p0, 1);
        p0 += __shfl_xor_sync(0xffffffffu, p0, 2);
        p1 += __shfl_xor_sync(0xffffffffu, p1, 1);
        p1 += __shfl_xor_sync(0xffffffffu, p1, 2);
        float i0 = 1.f / ((float)S_LEN + p0), i1 = 1.f / ((float)S_LEN + p1);
        int rr = rq + mi * 16;
        #pragma unroll
        for (int j = 0; j < 8; j++) {
            int col = j * 8 + cq;
            float a0 = (vs[col] + oacc[mi][j][0]) * i0;
            float a1 = (vs[col + 1] + oacc[mi][j][1]) * i0;
            float a2 = (vs[col] + oacc[mi][j][2]) * i1;
            float a3 = (vs[col + 1] + oacc[mi][j][3]) * i1;
            *(uint32_t*)(g_oh + ((size_t)(b * S_LEN + rr)) * EMB + h * DH + col) =
                packbf(a0, a1);
            *(uint32_t*)(g_oh + ((size_t)(b * S_LEN + rr + 8)) * EMB + h * DH + col) =
                packbf(a2, a3);
        }
    }
}

// ---------------------------------------------------------------------------
// Launch
// ---------------------------------------------------------------------------
extern "C" void kernel_launch(void* const* d_in, const int* in_sizes, int n_in,
                              void* d_out, int out_size) {
    const float* input = (const float*)d_in[0];
    const float* gamma = (const float*)d_in[1];
    const float* beta  = (const float*)d_in[2];
    const float* wq = (const float*)d_in[3];
    const float* bq = (const float*)d_in[4];
    const float* wk = (const float*)d_in[5];
    const float* bk = (const float*)d_in[6];
    const float* wv = (const float*)d_in[7];
    const float* bv = (const float*)d_in[8];
    const float* wo = (const float*)d_in[9];
    const float* bo = (const float*)d_in[10];
    float* out = (float*)d_out;

    gn_stats<<<BATCH * GROUPS, 1024>>>(input);
    wconv<<<dim3(256, 4), 256>>>(wq, wk, wv, wo);
    norm_transpose<<<dim3(S_LEN / 128, EMB / 32, BATCH), 256>>>(input, gamma, beta);

    gemm_qkv<<<dim3(3 * EMB / GBN, (BATCH * S_LEN) / GBM), 256>>>(bq, bk, bv);

    m_partial<<<dim3(MPCH, NBH), 256>>>();
    m_reduce<<<NBH, 256>>>();
    attn_lin<<<dim3(S_LEN / 128, NBH), 128>>>();

    gemm_out<<<dim3(EMB / GBN, (BATCH * S_LEN) / GBM), 256>>>(bo, out, input);
}

// round 16
// speedup vs baseline: 1.0410x; 1.0354x over previous
#include <cuda_runtime.h>
#include <cuda_fp16.h>
#include <cstdint>

#define S_LEN  4096
#define EMB    512
#define HEADS  8
#define DH     64
#define BATCH  2
#define GROUPS 32
#define GSIZE  65536
#define GN_EPS 100000.0f
#define QSCALE 0.125f

// Scratch (device globals; allocation-free rule). All value tensors fp16.
__device__ __half g_xh[BATCH * S_LEN * EMB];        // normalized input, [b][s][d]
__device__ __half g_oh[BATCH * S_LEN * EMB];        // attention out, [b][s][h*64+d]
__device__ __half g_wh[4 * EMB * EMB];              // weights: q,k,v,o concat
__device__ float g_mu[BATCH * GROUPS];
__device__ float g_rstd[BATCH * GROUPS];
__device__ __half g_qh[BATCH * HEADS * S_LEN * DH]; // [b][h][s][dh], pre-scaled 1/8
__device__ __half g_kh[BATCH * HEADS * S_LEN * DH];
__device__ __half g_vh[BATCH * HEADS * S_LEN * DH];
#define NBH (BATCH * HEADS)
#define MPCH 32
#define MPSZ 4224
__device__ float g_mp[NBH * MPCH * MPSZ];
__device__ __half g_mtb[NBH * 64 * 64];             // M^T per head
__device__ float g_ks[NBH * 64];
__device__ float g_vs[NBH * 64];

// f16 x f16 -> f16 accumulate (2x rate vs f32 acc on legacy mma path)
__device__ __forceinline__ void mma16816h(uint32_t c[2], const uint32_t a[4],
                                          uint32_t b0, uint32_t b1) {
    asm volatile(
        "mma.sync.aligned.m16n8k16.row.col.f16.f16.f16.f16 "
        "{%0,%1},{%2,%3,%4,%5},{%6,%7},{%0,%1};\n"
        : "+r"(c[0]), "+r"(c[1])
        : "r"(a[0]), "r"(a[1]), "r"(a[2]), "r"(a[3]), "r"(b0), "r"(b1));
}
// f16 x f16 -> f32 accumulate (attn_lin)
__device__ __forceinline__ void mma16816f(float c[4], const uint32_t a[4],
                                          uint32_t b0, uint32_t b1) {
    asm volatile(
        "mma.sync.aligned.m16n8k16.row.col.f32.f16.f16.f32 "
        "{%0,%1,%2,%3},{%4,%5,%6,%7},{%8,%9},{%0,%1,%2,%3};\n"
        : "+f"(c[0]), "+f"(c[1]), "+f"(c[2]), "+f"(c[3])
        : "r"(a[0]), "r"(a[1]), "r"(a[2]), "r"(a[3]), "r"(b0), "r"(b1));
}
__device__ __forceinline__ uint32_t packh(float x, float y) {
    __half2 h = __floats2half2_rn(x, y);
    return *(uint32_t*)&h;
}
__device__ __forceinline__ float2 uph(uint32_t u) {
    return __half22float2(*(__half2*)&u);
}
__device__ __forceinline__ void ldsm4(uint32_t* r, const __half* p) {
    uint32_t a = (uint32_t)__cvta_generic_to_shared((void*)p);
    asm volatile("ldmatrix.sync.aligned.m8n8.x4.shared.b16 {%0,%1,%2,%3}, [%4];\n"
        : "=r"(r[0]), "=r"(r[1]), "=r"(r[2]), "=r"(r[3]) : "r"(a));
}
__device__ __forceinline__ void cpasync16(void* smem, const void* gmem) {
    uint32_t s = (uint32_t)__cvta_generic_to_shared(smem);
    asm volatile("cp.async.cg.shared.global [%0], [%1], 16;\n" :: "r"(s), "l"(gmem));
}
#define CP_COMMIT() asm volatile("cp.async.commit_group;\n" ::: "memory")
#define CP_WAIT(N)  asm volatile("cp.async.wait_group %0;\n" :: "n"(N) : "memory")

// ---------------------------------------------------------------------------
// 1) GroupNorm statistics
// ---------------------------------------------------------------------------
__global__ void gn_stats(const float* __restrict__ in) {
    int g = blockIdx.x;
    const float4* p = (const float4*)(in + (size_t)g * GSIZE);
    float s = 0.f, s2 = 0.f;
    for (int i = threadIdx.x; i < GSIZE / 4; i += 1024) {
        float4 f = p[i];
        s  += f.x + f.y + f.z + f.w;
        s2 += f.x * f.x + f.y * f.y + f.z * f.z + f.w * f.w;
    }
    __shared__ float ss[32], ss2[32];
    #pragma unroll
    for (int o = 16; o > 0; o >>= 1) {
        s  += __shfl_down_sync(0xffffffffu, s,  o);
        s2 += __shfl_down_sync(0xffffffffu, s2, o);
    }
    int lane = threadIdx.x & 31, w = threadIdx.x >> 5;
    if (lane == 0) { ss[w] = s; ss2[w] = s2; }
    __syncthreads();
    if (threadIdx.x == 0) {
        float ts = 0.f, ts2 = 0.f;
        #pragma unroll
        for (int i = 0; i < 32; i++) { ts += ss[i]; ts2 += ss2[i]; }
        float mean = ts / (float)GSIZE;
        float var  = ts2 / (float)GSIZE - mean * mean;
        g_mu[g]   = mean;
        g_rstd[g] = rsqrtf(var + GN_EPS);
    }
}

// ---------------------------------------------------------------------------
// 2) Normalize + affine + transpose (B,D,S) -> (B,S,D), fp16 out.
// ---------------------------------------------------------------------------
__global__ __launch_bounds__(256) void norm_transpose(const float* __restrict__ in,
                                                      const float* __restrict__ gamma,
                                                      const float* __restrict__ beta) {
    __shared__ float tile[32][129];
    int b = blockIdx.z, tid = threadIdx.x;
    int d0 = blockIdx.y * 32, s0 = blockIdx.x * 128;
    #pragma unroll
    for (int i = 0; i < 4; i++) {
        int idx = tid + i * 256;
        int d = idx >> 5, s4 = idx & 31;
        int gd = d0 + d;
        float4 f = *(const float4*)(in + ((size_t)b * EMB + gd) * S_LEN + s0 + s4 * 4);
        int grp = b * GROUPS + (gd >> 4);
        float sc = g_rstd[grp] * gamma[gd];
        float sh = beta[gd] - g_mu[grp] * sc;
        tile[d][s4 * 4 + 0] = f.x * sc + sh;
        tile[d][s4 * 4 + 1] = f.y * sc + sh;
        tile[d][s4 * 4 + 2] = f.z * sc + sh;
        tile[d][s4 * 4 + 3] = f.w * sc + sh;
    }
    __syncthreads();
    #pragma unroll
    for (int k = 0; k < 2; k++) {
        int u = tid + k * 256;
        int s = u >> 2, c8 = (u & 3) * 8;
        uint32_t r[4];
        #pragma unroll
        for (int e = 0; e < 4; e++)
            r[e] = packh(tile[c8 + 2 * e][s], tile[c8 + 2 * e + 1][s]);
        *(uint4*)(g_xh + ((size_t)b * S_LEN + s0 + s) * EMB + d0 + c8) = *(uint4*)r;
    }
}

// ---------------------------------------------------------------------------
// 2b) Weight conversion fp32 -> fp16
// ---------------------------------------------------------------------------
__global__ void wconv(const float* __restrict__ w0, const float* __restrict__ w1,
                      const float* __restrict__ w2, const float* __restrict__ w3) {
    const float* src = (blockIdx.y == 0) ? w0 : (blockIdx.y == 1) ? w1
                     : (blockIdx.y == 2) ? w2 : w3;
    __half* dst = g_wh + (size_t)blockIdx.y * EMB * EMB;
    int i = blockIdx.x * 256 + threadIdx.x;
    float4 f = ((const float4*)src)[i];
    *(uint32_t*)(dst + (size_t)i * 4)     = packh(f.x, f.y);
    *(uint32_t*)(dst + (size_t)i * 4 + 2) = packh(f.z, f.w);
}

// ---------------------------------------------------------------------------
// 3) fp16 GEMM (f16 accumulate): tile 128x128x32, 256 thr (4m x 2n warps,
//    warp 32x64), 2-stage cp.async ring, one sync per k-iter.
// ---------------------------------------------------------------------------
#define GBM 128
#define GBN 128
#define GBK 32
#define GPAD 40
#define STAGE_HF ((GBM + GBN) * GPAD)
#define NKS (EMB / GBK)
#define SMEM_BYTES 40960

__device__ __forceinline__ void g_load_stage(const __half* A, const __half* Wb,
                                             int m0, int k0, __half* S, int tid) {
    __half* As = S;
    __half* Bs = S + GBM * GPAD;
    #pragma unroll
    for (int i = 0; i < 2; i++) {
        int idx = tid + i * 256;
        int r = idx >> 2, q = idx & 3;
        cpasync16(As + r * GPAD + q * 8, A + (size_t)(m0 + r) * EMB + k0 + q * 8);
    }
    #pragma unroll
    for (int i = 0; i < 2; i++) {
        int idx = tid + i * 256;
        int r = idx >> 2, q = idx & 3;
        cpasync16(Bs + r * GPAD + q * 8, Wb + (size_t)r * EMB + k0 + q * 8);
    }
}

// acc[mi][ni][2]: packed f16 pairs; [0] = rows lr, [1] = rows lr+8
__device__ __forceinline__ void g_mainloop(const __half* A, const __half* Wb,
                                           int m0, uint32_t acc[2][8][2],
                                           char* smem_raw, int tid) {
    __half* S0 = (__half*)smem_raw;
    int w = tid >> 5, l = tid & 31;
    int wm = w & 3, wn = w >> 2;
    int lrow = l & 15, lcol = (l >> 4) * 8;

    g_load_stage(A, Wb, m0, 0, S0, tid);
    CP_COMMIT();

    for (int ks = 0; ks < NKS; ks++) {
        if (ks == 0) { CP_WAIT(0); } else { CP_WAIT(1); }
        __syncthreads();
        if (ks + 1 < NKS) {
            g_load_stage(A, Wb, m0, (ks + 1) * GBK, S0 + ((ks + 1) & 1) * STAGE_HF, tid);
            CP_COMMIT();
        }
        __half* Sc = S0 + (ks & 1) * STAGE_HF;
        __half* As = Sc;
        __half* Bs = Sc + GBM * GPAD;
        #pragma unroll
        for (int kk = 0; kk < 2; kk++) {
            uint32_t af[2][4], bt[4][4];
            #pragma unroll
            for (int mi = 0; mi < 2; mi++)
                ldsm4(af[mi], As + (wm * 32 + mi * 16 + lrow) * GPAD + kk * 16 + lcol);
            #pragma unroll
            for (int t = 0; t < 4; t++)
                ldsm4(bt[t], Bs + (wn * 64 + t * 16 + lrow) * GPAD + kk * 16 + lcol);
            #pragma unroll
            for (int mi = 0; mi < 2; mi++)
                #pragma unroll
                for (int t = 0; t < 4; t++) {
                    mma16816h(acc[mi][2 * t + 0], af[mi], bt[t][0], bt[t][2]);
                    mma16816h(acc[mi][2 * t + 1], af[mi], bt[t][1], bt[t][3]);
                }
        }
    }
}

// Fused Q/K/V projection; smem-staged coalesced store epilogue.
__global__ __launch_bounds__(256, 2) void gemm_qkv(const float* __restrict__ bq,
                                                   const float* __restrict__ bk,
                                                   const float* __restrict__ bv) {
    __shared__ __align__(16) char smem_raw[SMEM_BYTES];
    int tid = threadIdx.x, w = tid >> 5, l = tid & 31;
    int wm = w & 3, wn = w >> 2;
    int lr = l >> 2, cq = (l & 3) * 2;
    int n0g = blockIdx.x * GBN;
    int mode = n0g >> 9;
    int n0 = n0g & 511;
    int m0 = blockIdx.y * GBM;
    const float* bias = (mode == 0) ? bq : (mode == 1) ? bk : bv;

    uint32_t acc[2][8][2] = {};
    g_mainloop(g_xh, g_wh + (size_t)n0g * EMB, m0, acc, smem_raw, tid);

    int b   = m0 >> 12;
    int sm0 = m0 & 4095;

    __half* dst = (mode == 0) ? g_qh : (mode == 1) ? g_kh : g_vh;
    const float sc = (mode == 0) ? QSCALE : 1.0f;

    __syncthreads();
    __half* Tb = (__half*)smem_raw;                    // [128][136] fp16
    #pragma unroll
    for (int mi = 0; mi < 2; mi++) {
        int rl = wm * 32 + mi * 16 + lr;
        #pragma unroll
        for (int ni = 0; ni < 8; ni++) {
            int cl = wn * 64 + ni * 8 + cq;
            float b0 = bias[n0 + cl], b1 = bias[n0 + cl + 1];
            float2 f0 = uph(acc[mi][ni][0]);
            float2 f1 = uph(acc[mi][ni][1]);
            *(uint32_t*)(Tb + rl * 136 + cl)       = packh((f0.x + b0) * sc, (f0.y + b1) * sc);
            *(uint32_t*)(Tb + (rl + 8) * 136 + cl) = packh((f1.x + b0) * sc, (f1.y + b1) * sc);
        }
    }
    __syncthreads();
    int h0 = n0 >> 6;
    #pragma unroll
    for (int i = 0; i < 8; i++) {
        int idx = tid + i * 256;
        int row = idx >> 4, u = idx & 15;
        int h = h0 + (u >> 3), d8 = (u & 7) * 8;
        size_t hb = (size_t)(b * HEADS + h) * S_LEN;
        *(uint4*)(dst + (hb + sm0 + row) * DH + d8) = *(uint4*)(Tb + row * 136 + u * 8);
    }
}

// Output projection + residual, fp32 [B,D,S] out.
__global__ __launch_bounds__(256, 2) void gemm_out(const float* __restrict__ bias,
                                                   float* __restrict__ dout,
                                                   const float* __restrict__ residual) {
    __shared__ __align__(16) char smem_raw[SMEM_BYTES];
    int tid = threadIdx.x, w = tid >> 5, l = tid & 31;
    int wm = w & 3, wn = w >> 2;
    int lr = l >> 2, cq = (l & 3) * 2;
    int n0 = blockIdx.x * GBN;
    int m0 = blockIdx.y * GBM;

    uint32_t acc[2][8][2] = {};
    g_mainloop(g_oh, g_wh + (size_t)3 * EMB * EMB + (size_t)n0 * EMB, m0, acc, smem_raw, tid);

    int b   = m0 >> 12;
    int sm0 = m0 & 4095;

    float* Tf = (float*)smem_raw;                      // [64][132] fp32
    #pragma unroll
    for (int p = 0; p < 2; p++) {
        __syncthreads();
        if (wn == p) {
            #pragma unroll
            for (int mi = 0; mi < 2; mi++) {
                int rl = wm * 32 + mi * 16 + lr;
                #pragma unroll
                for (int ni = 0; ni < 8; ni++) {
                    int cl = ni * 8 + cq;
                    float b0 = bias[n0 + p * 64 + cl], b1 = bias[n0 + p * 64 + cl + 1];
                    float2 f0 = uph(acc[mi][ni][0]);
                    float2 f1 = uph(acc[mi][ni][1]);
                    Tf[cl * 132 + rl]           = f0.x + b0;
                    Tf[(cl + 1) * 132 + rl]     = f0.y + b1;
                    Tf[cl * 132 + rl + 8]       = f1.x + b0;
                    Tf[(cl + 1) * 132 + rl + 8] = f1.y + b1;
                }
            }
        }
        __syncthreads();
        #pragma unroll
        for (int i = 0; i < 8; i++) {
            int idx = tid + i * 256;
            int dd = idx >> 5, ch = idx & 31;
            float4 v = *(float4*)(Tf + dd * 132 + ch * 4);
            size_t oi = ((size_t)b * EMB + n0 + p * 64 + dd) * S_LEN + sm0 + ch * 4;
            float4 r = *(const float4*)(residual + oi);
            v.x += r.x; v.y += r.y; v.z += r.z; v.w += r.w;
            *(float4*)(dout + oi) = v;
        }
    }
}

// ---------------------------------------------------------------------------
// 4a) Linear attention: partial M^T = (K^T V)^T, Ksum, Vsum per (head, chunk).
// ---------------------------------------------------------------------------
__global__ __launch_bounds__(256) void m_partial() {
    __shared__ float Kf[128][64];
    __shared__ __half Vs[128][64];
    int tid = threadIdx.x;
    int chunk = blockIdx.x, bh = blockIdx.y;
    const __half* Kb = g_kh + ((size_t)bh * S_LEN + chunk * 128) * DH;
    const __half* Vb = g_vh + ((size_t)bh * S_LEN + chunk * 128) * DH;
    #pragma unroll
    for (int i = 0; i < 4; i++) {
        int idx = tid + i * 256;
        int r = idx >> 3, q = idx & 7;
        uint4 u = *(const uint4*)(Kb + (size_t)r * DH + q * 8);
        uint32_t ws[4] = {u.x, u.y, u.z, u.w};
        #pragma unroll
        for (int e = 0; e < 4; e++) {
            float2 f = uph(ws[e]);
            Kf[r][q * 8 + 2 * e]     = f.x;
            Kf[r][q * 8 + 2 * e + 1] = f.y;
        }
        *(uint4*)(&Vs[r][q * 8]) = *(const uint4*)(Vb + (size_t)r * DH + q * 8);
    }
    __syncthreads();

    int ti = tid & 15, tj = tid >> 4;
    int i0 = ti * 4, j0 = tj * 4;
    float acc[4][4] = {};
    #pragma unroll 4
    for (int s = 0; s < 128; s++) {
        float4 kf = *(float4*)(&Kf[s][i0]);
        uint2 vv = *(uint2*)(&Vs[s][j0]);
        float2 a01 = uph(vv.x), a23 = uph(vv.y);
        float vf[4] = {a01.x, a01.y, a23.x, a23.y};
        #pragma unroll
        for (int a = 0; a < 4; a++) {
            acc[a][0] += vf[a] * kf.x;
            acc[a][1] += vf[a] * kf.y;
            acc[a][2] += vf[a] * kf.z;
            acc[a][3] += vf[a] * kf.w;
        }
    }
    float* mp = g_mp + (size_t)(bh * MPCH + chunk) * MPSZ;
    #pragma unroll
    for (int a = 0; a < 4; a++)
        #pragma unroll
        for (int bb = 0; bb < 4; bb++)
            mp[(j0 + a) * 64 + i0 + bb] = acc[a][bb];

    if (tid < 64) {
        float s = 0.f;
        for (int r = 0; r < 128; r++) s += Kf[r][tid];
        mp[4096 + tid] = s;
    } else if (tid < 128) {
        int j = tid - 64;
        float s = 0.f;
        for (int r = 0; r < 128; r++) s += __half2float(Vs[r][j]);
        mp[4160 + j] = s;
    }
}

// 4b) Reduce partials -> g_mtb (fp16), g_ks, g_vs.
__global__ void m_reduce() {
    int bh = blockIdx.x, tid = threadIdx.x;
    for (int e = tid; e < MPSZ; e += 256) {
        float s = 0.f;
        #pragma unroll 8
        for (int c = 0; c < MPCH; c++)
            s += g_mp[(size_t)(bh * MPCH + c) * MPSZ + e];
        if (e < 4096)      g_mtb[bh * 4096 + e] = __float2half(s);
        else if (e < 4160) g_ks[bh * 64 + e - 4096] = s;
        else               g_vs[bh * 64 + e - 4160] = s;
    }
}

// 4c) O = (Vsum + Q M) / (4096 + Q Ksum).
__global__ __launch_bounds__(128) void attn_lin() {
    __shared__ __align__(16) __half Mts[64 * 72];
    __shared__ float ks[64], vs[64];
    int tid = threadIdx.x, w = tid >> 5, l = tid & 31;
    int qt = blockIdx.x, bh = blockIdx.y;

    #pragma unroll
    for (int i = 0; i < 4; i++) {
        int idx = tid + i * 128;
        int r = idx >> 3, q = idx & 7;
        *(uint4*)(Mts + r * 72 + q * 8) = *(const uint4*)(g_mtb + bh * 4096 + r * 64 + q * 8);
    }
    if (tid < 64) ks[tid] = g_ks[bh * 64 + tid];
    else vs[tid - 64] = g_vs[bh * 64 + tid - 64];
    __syncthreads();

    const __half* Qb = g_qh + (size_t)bh * S_LEN * DH;
    int cq = (l & 3) * 2;
    int rq = qt * 128 + w * 32 + (l >> 2);
    uint32_t qf[2][4][4];
    #pragma unroll
    for (int mi = 0; mi < 2; mi++) {
        int rr = rq + mi * 16;
        #pragma unroll
        for (int kk = 0; kk < 4; kk++) {
            int c = kk * 16 + cq;
            qf[mi][kk][0] = *(const uint32_t*)(Qb + (size_t)rr * DH + c);
            qf[mi][kk][1] = *(const uint32_t*)(Qb + (size_t)(rr + 8) * DH + c);
            qf[mi][kk][2] = *(const uint32_t*)(Qb + (size_t)rr * DH + c + 8);
            qf[mi][kk][3] = *(const uint32_t*)(Qb + (size_t)(rr + 8) * DH + c + 8);
        }
    }

    float oacc[2][8][4] = {};
    int lrow = l & 15, lcol = (l >> 4) * 8;
    #pragma unroll
    for (int kk = 0; kk < 4; kk++) {
        uint32_t bt[4][4];
        #pragma unroll
        for (int rg = 0; rg < 4; rg++)
            ldsm4(bt[rg], Mts + (rg * 16 + lrow) * 72 + kk * 16 + lcol);
        #pragma unroll
        for (int mi = 0; mi < 2; mi++)
            #pragma unroll
            for (int rg = 0; rg < 4; rg++) {
                mma16816f(oacc[mi][2 * rg + 0], qf[mi][kk], bt[rg][0], bt[rg][2]);
                mma16816f(oacc[mi][2 * rg + 1], qf[mi][kk], bt[rg][1], bt[rg][3]);
            }
    }

    int b = bh >> 3, h = bh & 7;
    #pragma unroll
    for (int mi = 0; mi < 2; mi++) {
        float p0 = 0.f, p1 = 0.f;
        #pragma unroll
        for (int kk = 0; kk < 4; kk++) {
            int c = kk * 16 + cq;
            float2 f0 = uph(qf[mi][kk][0]), f1 = uph(qf[mi][kk][1]);
            float2 f2 = uph(qf[mi][kk][2]), f3 = uph(qf[mi][kk][3]);
            p0 += f0.x * ks[c]     + f0.y * ks[c + 1];
            p0 += f2.x * ks[c + 8] + f2.y * ks[c + 9];
            p1 += f1.x * ks[c]     + f1.y * ks[c + 1];
            p1 += f3.x * ks[c + 8] + f3.y * ks[c + 9];
        }
        p0 += __shfl_xor_sync(0xffffffffu, p0, 1);
        p0 += __shfl_xor_sync(0xffffffffu, p0, 2);
        p1 += __shfl_xor_sync(0xffffffffu, p1, 1);
        p1 += __shfl_xor_sync(0xffffffffu, p1, 2);
        float i0 = 1.f / ((float)S_LEN + p0), i1 = 1.f / ((float)S_LEN + p1);
        int rr = rq + mi * 16;
        #pragma unroll
        for (int j = 0; j < 8; j++) {
            int col = j * 8 + cq;
            float a0 = (vs[col] + oacc[mi][j][0]) * i0;
            float a1 = (vs[col + 1] + oacc[mi][j][1]) * i0;
            float a2 = (vs[col] + oacc[mi][j][2]) * i1;
            float a3 = (vs[col + 1] + oacc[mi][j][3]) * i1;
            *(uint32_t*)(g_oh + ((size_t)(b * S_LEN + rr)) * EMB + h * DH + col) =
                packh(a0, a1);
            *(uint32_t*)(g_oh + ((size_t)(b * S_LEN + rr + 8)) * EMB + h * DH + col) =
                packh(a2, a3);
        }
    }
}

// ---------------------------------------------------------------------------
extern "C" void kernel_launch(void* const* d_in, const int* in_sizes, int n_in,
                              void* d_out, int out_size) {
    const float* input = (const float*)d_in[0];
    const float* gamma = (const float*)d_in[1];
    const float* beta  = (const float*)d_in[2];
    const float* wq = (const float*)d_in[3];
    const float* bq = (const float*)d_in[4];
    const float* wk = (const float*)d_in[5];
    const float* bk = (const float*)d_in[6];
    const float* wv = (const float*)d_in[7];
    const float* bv = (const float*)d_in[8];
    const float* wo = (const float*)d_in[9];
    const float* bo = (const float*)d_in[10];
    float* out = (float*)d_out;

    gn_stats<<<BATCH * GROUPS, 1024>>>(input);
    wconv<<<dim3(256, 4), 256>>>(wq, wk, wv, wo);
    norm_transpose<<<dim3(S_LEN / 128, EMB / 32, BATCH), 256>>>(input, gamma, beta);

    gemm_qkv<<<dim3(3 * EMB / GBN, (BATCH * S_LEN) / GBM), 256>>>(bq, bk, bv);

    m_partial<<<dim3(MPCH, NBH), 256>>>();
    m_reduce<<<NBH, 256>>>();
    attn_lin<<<dim3(S_LEN / 128, NBH), 128>>>();

    gemm_out<<<dim3(EMB / GBN, (BATCH * S_LEN) / GBM), 256>>>(bo, out, input);
}